// round 12
// baseline (speedup 1.0000x reference)
#include <cuda_runtime.h>
#include <cuda_fp16.h>
#include <cstdint>

#define BB 32
#define NN 2048
#define DD 512
#define KC 64
#define CC 80              // K + G
#define BN_TOT (BB*NN)     // 65536
#define BN_EPS_F 1e-5f

// ---------------- scratch (device globals; no allocation allowed) ----------------
__device__ __half g_assn[(size_t)BN_TOT * CC];        // raw assignments fp16 [row][80]
__device__ __half g_xhT[(size_t)BB * DD * NN];        // x fp16 transposed [b][d][n]
__device__ __half g_chT[CC * DD];                     // clusters^T fp16 [c][d]
__device__ __half g_assnT[(size_t)BB * KC * NN];      // softmaxed assn^T [b][k][n]
__device__ float  g_colsum[CC], g_colsq[CC];
__device__ float  g_asum[BB * KC];
__device__ float  g_vladT[(size_t)BB * KC * DD];      // vlad fp32 [b][k][d]
__device__ float  g_colnorm[BB * KC];

// ---------------- helpers ----------------
__device__ __forceinline__ void mma16816(float* c, const uint32_t* a, const uint32_t* b) {
    asm volatile(
        "mma.sync.aligned.m16n8k16.row.col.f32.f16.f16.f32 "
        "{%0,%1,%2,%3}, {%4,%5,%6,%7}, {%8,%9}, {%0,%1,%2,%3};\n"
        : "+f"(c[0]), "+f"(c[1]), "+f"(c[2]), "+f"(c[3])
        : "r"(a[0]), "r"(a[1]), "r"(a[2]), "r"(a[3]), "r"(b[0]), "r"(b[1]));
}
__device__ __forceinline__ uint32_t smemu32(const void* p) {
    return (uint32_t)__cvta_generic_to_shared(p);
}
__device__ __forceinline__ void cpasync16(void* smem, const void* g) {
    asm volatile("cp.async.cg.shared.global [%0], [%1], 16;\n"
                 :: "r"(smemu32(smem)), "l"(g));
}

// ---------------- kernel 0: zero accumulators + clusters^T to fp16 ----------------
__global__ void k_init(const float* __restrict__ clusters) {
    int tid = blockIdx.x * blockDim.x + threadIdx.x;
    if (tid < CC) { g_colsum[tid] = 0.f; g_colsq[tid] = 0.f; }
    if (tid < BB * KC) { g_asum[tid] = 0.f; g_colnorm[tid] = 0.f; }
    for (int i = tid; i < CC * DD; i += gridDim.x * blockDim.x) {
        int c = i / DD, d = i % DD;
        g_chT[i] = __float2half(clusters[d * CC + c]);
    }
}

// ---------------- kernel 1: assn = x @ clusters + xhT + FUSED column stats ----------------
// grid 512 x 256 thr. Block: 128 rows x 80 cols, K=512 in EIGHT chunks of 64. Pipelined.
__global__ void __launch_bounds__(256, 2) k_gemm1(const float* __restrict__ x) {
    __shared__ __align__(16) __half sA[128 * 72];
    __shared__ __align__(16) __half sB[80 * 72];
    __shared__ float sSum[CC], sSq[CC];
    const int tid = threadIdx.x;
    const int warp = tid >> 5, lane = tid & 31;
    const int g = lane >> 2, t = lane & 3;
    const int wm = warp >> 1, wn = warp & 1;
    const int row0 = blockIdx.x * 128;
    const int b = row0 >> 11;
    const int n0 = row0 & 2047;

    if (tid < CC) { sSum[tid] = 0.f; sSq[tid] = 0.f; }

    float acc[2][5][4] = {};
    const int dl = tid & 63;   // d-within-stage for xhT transpose write
    const int q  = tid >> 6;   // n quarter

    // preload stage-0 x chunk into registers
    float4 rx[8];
    #pragma unroll
    for (int it = 0; it < 8; ++it) {
        int flat = (it * 256 + tid) * 4;
        int r = flat >> 6, c = flat & 63;
        rx[it] = *(const float4*)&x[(size_t)(row0 + r) * DD + c];
    }

    #pragma unroll
    for (int k0s = 0; k0s < 8; ++k0s) {          // 8 chunks × 64 = 512 = DD
        const int k0 = k0s * 64;
        // clusters^T tile via cp.async (80 rows x 64 halfs)
        #pragma unroll
        for (int it = 0; it < 3; ++it) {
            int id = it * 256 + tid;
            if (id < 640) {
                int c = id >> 3, c8 = id & 7;
                cpasync16(&sB[c * 72 + c8 * 8], &g_chT[c * DD + k0 + c8 * 8]);
            }
        }
        // convert + store A tile from registers
        #pragma unroll
        for (int it = 0; it < 8; ++it) {
            int flat = (it * 256 + tid) * 4;
            int r = flat >> 6, c = flat & 63;
            __half2* dst = (__half2*)&sA[r * 72 + c];
            dst[0] = __floats2half2_rn(rx[it].x, rx[it].y);
            dst[1] = __floats2half2_rn(rx[it].z, rx[it].w);
        }
        asm volatile("cp.async.commit_group;\n");
        // prefetch next x chunk (overlaps xhT write + mma below)
        if (k0s < 7) {
            #pragma unroll
            for (int it = 0; it < 8; ++it) {
                int flat = (it * 256 + tid) * 4;
                int r = flat >> 6, c = flat & 63;
                rx[it] = *(const float4*)&x[(size_t)(row0 + r) * DD + k0 + 64 + c];
            }
        }
        asm volatile("cp.async.wait_group 0;\n");
        __syncthreads();
        // side-effect: write x fp16 transposed [b][d][n]
        {
            size_t base = ((size_t)(b * DD + k0 + dl)) * NN + n0 + q * 32;
            #pragma unroll
            for (int s0 = 0; s0 < 32; s0 += 8) {
                __half tmp[8];
                #pragma unroll
                for (int j = 0; j < 8; ++j) tmp[j] = sA[(q * 32 + s0 + j) * 72 + dl];
                *(uint4*)&g_xhT[base + s0] = *(const uint4*)tmp;
            }
        }
        // mma over 4 k-steps of 16
        #pragma unroll
        for (int ks = 0; ks < 64; ks += 16) {
            uint32_t af[2][4], bf[5][2];
            #pragma unroll
            for (int mf = 0; mf < 2; ++mf) {
                const __half* base = &sA[(wm * 32 + mf * 16 + g) * 72 + ks + 2 * t];
                af[mf][0] = *(const uint32_t*)base;
                af[mf][1] = *(const uint32_t*)(base + 8 * 72);
                af[mf][2] = *(const uint32_t*)(base + 8);
                af[mf][3] = *(const uint32_t*)(base + 8 * 72 + 8);
            }
            #pragma unroll
            for (int nf = 0; nf < 5; ++nf) {
                const __half* base = &sB[(wn * 40 + nf * 8 + g) * 72 + ks + 2 * t];
                bf[nf][0] = *(const uint32_t*)base;
                bf[nf][1] = *(const uint32_t*)(base + 8);
            }
            #pragma unroll
            for (int mf = 0; mf < 2; ++mf)
                #pragma unroll
                for (int nf = 0; nf < 5; ++nf)
                    mma16816(acc[mf][nf], af[mf], bf[nf]);
        }
        __syncthreads();
    }
    // write raw assn (fp16)
    #pragma unroll
    for (int mf = 0; mf < 2; ++mf) {
        int r = row0 + wm * 32 + mf * 16 + g;
        #pragma unroll
        for (int nf = 0; nf < 5; ++nf) {
            int c = wn * 40 + nf * 8 + 2 * t;
            *(__half2*)&g_assn[(size_t)r * CC + c]       = __floats2half2_rn(acc[mf][nf][0], acc[mf][nf][1]);
            *(__half2*)&g_assn[(size_t)(r + 8) * CC + c] = __floats2half2_rn(acc[mf][nf][2], acc[mf][nf][3]);
        }
    }
    // FUSED column stats (each (row,col) counted exactly once across the grid)
    float ps[10], pq[10];
    #pragma unroll
    for (int nf = 0; nf < 5; ++nf)
        #pragma unroll
        for (int j = 0; j < 2; ++j) {
            float a0 = acc[0][nf][j], a1 = acc[0][nf][j + 2];
            float a2 = acc[1][nf][j], a3 = acc[1][nf][j + 2];
            ps[nf * 2 + j] = a0 + a1 + a2 + a3;
            pq[nf * 2 + j] = a0 * a0 + a1 * a1 + a2 * a2 + a3 * a3;
        }
    #pragma unroll
    for (int o = 16; o >= 4; o >>= 1)     // reduce over g (lane bits 2..4)
        #pragma unroll
        for (int i = 0; i < 10; ++i) {
            ps[i] += __shfl_xor_sync(0xffffffffu, ps[i], o);
            pq[i] += __shfl_xor_sync(0xffffffffu, pq[i], o);
        }
    if (g == 0) {
        #pragma unroll
        for (int nf = 0; nf < 5; ++nf)
            #pragma unroll
            for (int j = 0; j < 2; ++j) {
                int c = wn * 40 + nf * 8 + 2 * t + j;
                atomicAdd(&sSum[c], ps[nf * 2 + j]);
                atomicAdd(&sSq[c],  pq[nf * 2 + j]);
            }
    }
    __syncthreads();
    if (tid < CC) {
        atomicAdd(&g_colsum[tid], sSum[tid]);
        atomicAdd(&g_colsq[tid],  sSq[tid]);
    }
}

// ---------------- kernel 2: (BN-finalize fused) + softmax + assn^T fp16 + a_sum ----------------
#define STS 132
__global__ void __launch_bounds__(256) k_softmax(const float* __restrict__ gamma,
                                                 const float* __restrict__ beta) {
    __shared__ __half sT[64 * STS];
    __shared__ float sAsum[64];
    __shared__ float sSc[CC], sBi[CC];
    int tid = threadIdx.x, warp = tid >> 5, lane = tid & 31;
    int row0 = blockIdx.x * 128;
    int b = row0 >> 11, n0 = row0 & 2047;
    if (tid < 64) sAsum[tid] = 0.f;
    if (tid < CC) {
        float inv = 1.0f / (float)BN_TOT;
        float mean = g_colsum[tid] * inv;
        float var  = g_colsq[tid] * inv - mean * mean;
        float sc = rsqrtf(var + BN_EPS_F) * gamma[tid];
        sSc[tid] = sc;
        sBi[tid] = beta[tid] - mean * sc;
    }
    __syncthreads();
    float sc0 = sSc[lane],      bi0 = sBi[lane];
    float sc1 = sSc[lane + 32], bi1 = sBi[lane + 32];
    float sc2 = 0.f, bi2 = 0.f;
    if (lane < 16) { sc2 = sSc[lane + 64]; bi2 = sBi[lane + 64]; }
    float acc0 = 0.f, acc1 = 0.f;
    #pragma unroll
    for (int it = 0; it < 8; ++it) {
        int nlA = warp + it * 16, nlB = nlA + 8;
        const __half* pa = g_assn + (size_t)(row0 + nlA) * CC;
        const __half* pb = g_assn + (size_t)(row0 + nlB) * CC;
        float a0 = __half2float(pa[lane]) * sc0 + bi0;
        float b0 = __half2float(pb[lane]) * sc0 + bi0;
        float a1 = __half2float(pa[lane + 32]) * sc1 + bi1;
        float b1 = __half2float(pb[lane + 32]) * sc1 + bi1;
        float a2 = (lane < 16) ? (__half2float(pa[lane + 64]) * sc2 + bi2) : -1e30f;
        float b2 = (lane < 16) ? (__half2float(pb[lane + 64]) * sc2 + bi2) : -1e30f;
        float ma = fmaxf(fmaxf(a0, a1), a2);
        float mb = fmaxf(fmaxf(b0, b1), b2);
        #pragma unroll
        for (int o = 16; o; o >>= 1) {
            ma = fmaxf(ma, __shfl_xor_sync(0xffffffffu, ma, o));
            mb = fmaxf(mb, __shfl_xor_sync(0xffffffffu, mb, o));
        }
        float ea0 = __expf(a0 - ma), ea1 = __expf(a1 - ma);
        float eb0 = __expf(b0 - mb), eb1 = __expf(b1 - mb);
        float ea2 = (lane < 16) ? __expf(a2 - ma) : 0.f;
        float eb2 = (lane < 16) ? __expf(b2 - mb) : 0.f;
        float sa = ea0 + ea1 + ea2;
        float sb = eb0 + eb1 + eb2;
        #pragma unroll
        for (int o = 16; o; o >>= 1) {
            sa += __shfl_xor_sync(0xffffffffu, sa, o);
            sb += __shfl_xor_sync(0xffffffffu, sb, o);
        }
        float ia = 1.0f / sa, ib = 1.0f / sb;
        float pA0 = ea0 * ia, pA1 = ea1 * ia;
        float pB0 = eb0 * ib, pB1 = eb1 * ib;
        acc0 += pA0 + pB0; acc1 += pA1 + pB1;
        sT[lane * STS + nlA]        = __float2half(pA0);
        sT[(lane + 32) * STS + nlA] = __float2half(pA1);
        sT[lane * STS + nlB]        = __float2half(pB0);
        sT[(lane + 32) * STS + nlB] = __float2half(pB1);
    }
    atomicAdd(&sAsum[lane], acc0);
    atomicAdd(&sAsum[lane + 32], acc1);
    __syncthreads();
    int kc = tid >> 2, seg = tid & 3;
    size_t base = ((size_t)(b * KC + kc)) * NN + n0 + seg * 32;
    const __half* src = &sT[kc * STS + seg * 32];
    #pragma unroll
    for (int j = 0; j < 8; ++j)
        *(uint2*)&g_assnT[base + j * 4] = *(const uint2*)&src[j * 4];
    if (tid < 64) atomicAdd(&g_asum[b * KC + tid], sAsum[tid]);
}

// ---------------- kernel 3: vlad^T = assn^T @ x - a_sum*clusters2 — 64k x 64d tiles ----------------
// grid 256 (32 b x 8 d-tiles), 256 thr, 2 CTAs/SM. n-chunks of 32, double-buffered. smem 20.5KB.
#define SAW 40   // 32 + 8 pad (halfs)
__global__ void __launch_bounds__(256, 2) k_gemm2(const float* __restrict__ clusters2) {
    __shared__ __align__(16) __half sA[2][64 * SAW];    // assnT tile [kc][n32]
    __shared__ __align__(16) __half sB[2][64 * SAW];    // xhT tile   [d][n32]
    int tid = threadIdx.x, warp = tid >> 5, lane = tid & 31;
    int g = lane >> 2, t = lane & 3;
    int b = blockIdx.x >> 3;
    int d0 = (blockIdx.x & 7) * 64;
    float acc[4][4] = {};
    const __half* Abase = g_assnT + (size_t)b * KC * NN;
    const __half* Bbase = g_xhT + ((size_t)b * DD + d0) * NN;

    const int a_r = tid >> 2, a_c = tid & 3;            // 64 rows x 4 16B-chunks
    // prologue: stage 0
    {
        cpasync16(&sA[0][a_r * SAW + a_c * 8], &Abase[(size_t)a_r * NN + a_c * 8]);
        cpasync16(&sB[0][a_r * SAW + a_c * 8], &Bbase[(size_t)a_r * NN + a_c * 8]);
        asm volatile("cp.async.commit_group;\n");
    }
    for (int s = 0; s < 64; ++s) {
        int buf = s & 1;
        if (s < 63) {
            int nn0 = (s + 1) * 32, nb = buf ^ 1;
            cpasync16(&sA[nb][a_r * SAW + a_c * 8], &Abase[(size_t)a_r * NN + nn0 + a_c * 8]);
            cpasync16(&sB[nb][a_r * SAW + a_c * 8], &Bbase[(size_t)a_r * NN + nn0 + a_c * 8]);
            asm volatile("cp.async.commit_group;\n");
            asm volatile("cp.async.wait_group 1;\n");
        } else {
            asm volatile("cp.async.wait_group 0;\n");
        }
        __syncthreads();
        #pragma unroll
        for (int ks = 0; ks < 32; ks += 16) {
            uint32_t af[4][4], bf[2];
            #pragma unroll
            for (int mf = 0; mf < 4; ++mf) {
                const __half* base = &sA[buf][(mf * 16 + g) * SAW + ks + 2 * t];
                af[mf][0] = *(const uint32_t*)base;
                af[mf][1] = *(const uint32_t*)(base + 8 * SAW);
                af[mf][2] = *(const uint32_t*)(base + 8);
                af[mf][3] = *(const uint32_t*)(base + 8 * SAW + 8);
            }
            {
                const __half* base = &sB[buf][(warp * 8 + g) * SAW + ks + 2 * t];
                bf[0] = *(const uint32_t*)base;
                bf[1] = *(const uint32_t*)(base + 8);
            }
            #pragma unroll
            for (int mf = 0; mf < 4; ++mf)
                mma16816(acc[mf], af[mf], bf);
        }
        __syncthreads();
    }
    // epilogue: subtract a_sum*clusters2, write vladT fp32, accumulate column sq-norms
    #pragma unroll
    for (int mf = 0; mf < 4; ++mf) {
        #pragma unroll
        for (int h = 0; h < 2; ++h) {
            int kc = mf * 16 + g + h * 8;
            float asv = g_asum[b * KC + kc];
            int d = d0 + warp * 8 + 2 * t;
            float v0 = acc[mf][h * 2 + 0] - asv * clusters2[(size_t)d * KC + kc];
            float v1 = acc[mf][h * 2 + 1] - asv * clusters2[(size_t)(d + 1) * KC + kc];
            *(float2*)&g_vladT[((size_t)b * KC + kc) * DD + d] = make_float2(v0, v1);
            float nsq = v0 * v0 + v1 * v1;
            nsq += __shfl_xor_sync(0xffffffffu, nsq, 1);
            nsq += __shfl_xor_sync(0xffffffffu, nsq, 2);
            if (t == 0) atomicAdd(&g_colnorm[b * KC + kc], nsq);
        }
    }
}

// ---------------- kernel 4: (scales fused) + scale + transpose to out[b][d][k] ----------------
__global__ void __launch_bounds__(256) k_output(float* __restrict__ out) {
    __shared__ float sT[64][65];
    __shared__ float sR[64], sC[64];
    __shared__ float sTot;
    int tid = threadIdx.x;
    int b = blockIdx.x >> 3;
    int d0 = (blockIdx.x & 7) * 64;
    if (tid < 64) {
        float nsq = g_colnorm[b * KC + tid];
        float r = 1.0f / fmaxf(sqrtf(nsq), 1e-12f);
        sR[tid] = r;
        sC[tid] = nsq * r * r;   // ||col||^2 after intra-norm
    }
    __syncthreads();
    if (tid < 32) {
        float s = sC[tid] + sC[tid + 32];
        #pragma unroll
        for (int o = 16; o; o >>= 1) s += __shfl_xor_sync(0xffffffffu, s, o);
        if (tid == 0) sTot = s;
    }
    __syncthreads();
    float ginv = 1.0f / fmaxf(sqrtf(sTot), 1e-12f);
    {
        int kc = tid >> 2, seg = tid & 3;
        float s = sR[kc] * ginv;
        const float* src = &g_vladT[((size_t)b * KC + kc) * DD + d0 + seg * 16];
        #pragma unroll
        for (int j = 0; j < 4; ++j) {
            float4 v = *(const float4*)&src[j * 4];
            sT[kc][seg * 16 + j * 4 + 0] = v.x * s;
            sT[kc][seg * 16 + j * 4 + 1] = v.y * s;
            sT[kc][seg * 16 + j * 4 + 2] = v.z * s;
            sT[kc][seg * 16 + j * 4 + 3] = v.w * s;
        }
    }
    __syncthreads();
    {
        int d = tid >> 2, k0 = (tid & 3) * 16;
        float* dst = &out[(size_t)b * (DD * KC) + (size_t)(d0 + d) * KC + k0];
        #pragma unroll
        for (int j = 0; j < 4; ++j) {
            float4 v;
            v.x = sT[k0 + j * 4 + 0][d];
            v.y = sT[k0 + j * 4 + 1][d];
            v.z = sT[k0 + j * 4 + 2][d];
            v.w = sT[k0 + j * 4 + 3][d];
            *(float4*)&dst[j * 4] = v;
        }
    }
}

// ---------------- launch ----------------
extern "C" void kernel_launch(void* const* d_in, const int* in_sizes, int n_in,
                              void* d_out, int out_size) {
    (void)in_sizes; (void)n_in; (void)out_size;
    const float* x         = (const float*)d_in[0];
    const float* clusters  = (const float*)d_in[1];
    const float* clusters2 = (const float*)d_in[2];
    const float* gamma     = (const float*)d_in[3];
    const float* beta      = (const float*)d_in[4];
    float* out = (float*)d_out;

    k_init<<<64, 256>>>(clusters);
    k_gemm1<<<512, 256>>>(x);
    k_softmax<<<512, 256>>>(gamma, beta);
    k_gemm2<<<256, 256>>>(clusters2);
    k_output<<<256, 256>>>(out);
}

// round 13
// speedup vs baseline: 1.0167x; 1.0167x over previous
#include <cuda_runtime.h>
#include <cuda_fp16.h>
#include <cstdint>

#define BB 32
#define NN 2048
#define DD 512
#define KC 64
#define CC 80              // K + G
#define BN_TOT (BB*NN)     // 65536
#define BN_EPS_F 1e-5f

// ---------------- scratch (device globals; no allocation allowed) ----------------
__device__ __half g_assn[(size_t)BN_TOT * CC];        // raw assignments fp16 [row][80]
__device__ __half g_xhT[(size_t)BB * DD * NN];        // x fp16 transposed [b][d][n]
__device__ __half g_chT[CC * DD];                     // clusters^T fp16 [c][d]
__device__ __half g_assnT[(size_t)BB * KC * NN];      // softmaxed assn^T [b][k][n]
__device__ float  g_colsum[CC], g_colsq[CC];
__device__ float  g_asum[BB * KC];
__device__ float  g_vladT[(size_t)BB * KC * DD];      // vlad fp32 [b][k][d]
__device__ float  g_colnorm[BB * KC];

// ---------------- helpers ----------------
__device__ __forceinline__ void mma16816(float* c, const uint32_t* a, const uint32_t* b) {
    asm volatile(
        "mma.sync.aligned.m16n8k16.row.col.f32.f16.f16.f32 "
        "{%0,%1,%2,%3}, {%4,%5,%6,%7}, {%8,%9}, {%0,%1,%2,%3};\n"
        : "+f"(c[0]), "+f"(c[1]), "+f"(c[2]), "+f"(c[3])
        : "r"(a[0]), "r"(a[1]), "r"(a[2]), "r"(a[3]), "r"(b[0]), "r"(b[1]));
}
__device__ __forceinline__ uint32_t smemu32(const void* p) {
    return (uint32_t)__cvta_generic_to_shared(p);
}
__device__ __forceinline__ void cpasync16(void* smem, const void* g) {
    asm volatile("cp.async.cg.shared.global [%0], [%1], 16;\n"
                 :: "r"(smemu32(smem)), "l"(g));
}

// ---------------- kernel 0: zero accumulators + clusters^T to fp16 ----------------
__global__ void k_init(const float* __restrict__ clusters) {
    int tid = blockIdx.x * blockDim.x + threadIdx.x;
    if (tid < CC) { g_colsum[tid] = 0.f; g_colsq[tid] = 0.f; }
    if (tid < BB * KC) { g_asum[tid] = 0.f; g_colnorm[tid] = 0.f; }
    for (int i = tid; i < CC * DD; i += gridDim.x * blockDim.x) {
        int c = i / DD, d = i % DD;
        g_chT[i] = __float2half(clusters[d * CC + c]);
    }
}

// ---------------- kernel 1: assn = x @ clusters + xhT + FUSED column stats ----------------
// grid 512 x 256 thr. Block: 128 rows x 80 cols, K=512 in EIGHT chunks of 64. Pipelined.
__global__ void __launch_bounds__(256, 2) k_gemm1(const float* __restrict__ x) {
    __shared__ __align__(16) __half sA[128 * 72];
    __shared__ __align__(16) __half sB[80 * 72];
    __shared__ float sSum[CC], sSq[CC];
    const int tid = threadIdx.x;
    const int warp = tid >> 5, lane = tid & 31;
    const int g = lane >> 2, t = lane & 3;
    const int wm = warp >> 1, wn = warp & 1;
    const int row0 = blockIdx.x * 128;
    const int b = row0 >> 11;
    const int n0 = row0 & 2047;

    if (tid < CC) { sSum[tid] = 0.f; sSq[tid] = 0.f; }

    float acc[2][5][4] = {};
    const int dl = tid & 63;   // d-within-stage for xhT transpose write
    const int q  = tid >> 6;   // n quarter

    // preload stage-0 x chunk into registers
    float4 rx[8];
    #pragma unroll
    for (int it = 0; it < 8; ++it) {
        int flat = (it * 256 + tid) * 4;
        int r = flat >> 6, c = flat & 63;
        rx[it] = *(const float4*)&x[(size_t)(row0 + r) * DD + c];
    }

    #pragma unroll
    for (int k0s = 0; k0s < 8; ++k0s) {          // 8 chunks × 64 = 512 = DD
        const int k0 = k0s * 64;
        // clusters^T tile via cp.async (80 rows x 64 halfs)
        #pragma unroll
        for (int it = 0; it < 3; ++it) {
            int id = it * 256 + tid;
            if (id < 640) {
                int c = id >> 3, c8 = id & 7;
                cpasync16(&sB[c * 72 + c8 * 8], &g_chT[c * DD + k0 + c8 * 8]);
            }
        }
        // convert + store A tile from registers
        #pragma unroll
        for (int it = 0; it < 8; ++it) {
            int flat = (it * 256 + tid) * 4;
            int r = flat >> 6, c = flat & 63;
            __half2* dst = (__half2*)&sA[r * 72 + c];
            dst[0] = __floats2half2_rn(rx[it].x, rx[it].y);
            dst[1] = __floats2half2_rn(rx[it].z, rx[it].w);
        }
        asm volatile("cp.async.commit_group;\n");
        // prefetch next x chunk (overlaps xhT write + mma below)
        if (k0s < 7) {
            #pragma unroll
            for (int it = 0; it < 8; ++it) {
                int flat = (it * 256 + tid) * 4;
                int r = flat >> 6, c = flat & 63;
                rx[it] = *(const float4*)&x[(size_t)(row0 + r) * DD + k0 + 64 + c];
            }
        }
        asm volatile("cp.async.wait_group 0;\n");
        __syncthreads();
        // side-effect: write x fp16 transposed [b][d][n]
        {
            size_t base = ((size_t)(b * DD + k0 + dl)) * NN + n0 + q * 32;
            #pragma unroll
            for (int s0 = 0; s0 < 32; s0 += 8) {
                __half tmp[8];
                #pragma unroll
                for (int j = 0; j < 8; ++j) tmp[j] = sA[(q * 32 + s0 + j) * 72 + dl];
                *(uint4*)&g_xhT[base + s0] = *(const uint4*)tmp;
            }
        }
        // mma over 4 k-steps of 16
        #pragma unroll
        for (int ks = 0; ks < 64; ks += 16) {
            uint32_t af[2][4], bf[5][2];
            #pragma unroll
            for (int mf = 0; mf < 2; ++mf) {
                const __half* base = &sA[(wm * 32 + mf * 16 + g) * 72 + ks + 2 * t];
                af[mf][0] = *(const uint32_t*)base;
                af[mf][1] = *(const uint32_t*)(base + 8 * 72);
                af[mf][2] = *(const uint32_t*)(base + 8);
                af[mf][3] = *(const uint32_t*)(base + 8 * 72 + 8);
            }
            #pragma unroll
            for (int nf = 0; nf < 5; ++nf) {
                const __half* base = &sB[(wn * 40 + nf * 8 + g) * 72 + ks + 2 * t];
                bf[nf][0] = *(const uint32_t*)base;
                bf[nf][1] = *(const uint32_t*)(base + 8);
            }
            #pragma unroll
            for (int mf = 0; mf < 2; ++mf)
                #pragma unroll
                for (int nf = 0; nf < 5; ++nf)
                    mma16816(acc[mf][nf], af[mf], bf[nf]);
        }
        __syncthreads();
    }
    // write raw assn (fp16)
    #pragma unroll
    for (int mf = 0; mf < 2; ++mf) {
        int r = row0 + wm * 32 + mf * 16 + g;
        #pragma unroll
        for (int nf = 0; nf < 5; ++nf) {
            int c = wn * 40 + nf * 8 + 2 * t;
            *(__half2*)&g_assn[(size_t)r * CC + c]       = __floats2half2_rn(acc[mf][nf][0], acc[mf][nf][1]);
            *(__half2*)&g_assn[(size_t)(r + 8) * CC + c] = __floats2half2_rn(acc[mf][nf][2], acc[mf][nf][3]);
        }
    }
    // FUSED column stats (each (row,col) counted exactly once across the grid)
    float ps[10], pq[10];
    #pragma unroll
    for (int nf = 0; nf < 5; ++nf)
        #pragma unroll
        for (int j = 0; j < 2; ++j) {
            float a0 = acc[0][nf][j], a1 = acc[0][nf][j + 2];
            float a2 = acc[1][nf][j], a3 = acc[1][nf][j + 2];
            ps[nf * 2 + j] = a0 + a1 + a2 + a3;
            pq[nf * 2 + j] = a0 * a0 + a1 * a1 + a2 * a2 + a3 * a3;
        }
    #pragma unroll
    for (int o = 16; o >= 4; o >>= 1)     // reduce over g (lane bits 2..4)
        #pragma unroll
        for (int i = 0; i < 10; ++i) {
            ps[i] += __shfl_xor_sync(0xffffffffu, ps[i], o);
            pq[i] += __shfl_xor_sync(0xffffffffu, pq[i], o);
        }
    if (g == 0) {
        #pragma unroll
        for (int nf = 0; nf < 5; ++nf)
            #pragma unroll
            for (int j = 0; j < 2; ++j) {
                int c = wn * 40 + nf * 8 + 2 * t + j;
                atomicAdd(&sSum[c], ps[nf * 2 + j]);
                atomicAdd(&sSq[c],  pq[nf * 2 + j]);
            }
    }
    __syncthreads();
    if (tid < CC) {
        atomicAdd(&g_colsum[tid], sSum[tid]);
        atomicAdd(&g_colsq[tid],  sSq[tid]);
    }
}

// ---------------- kernel 2: (BN-finalize fused) + softmax + assn^T fp16 + a_sum ----------------
#define STS 132
__global__ void __launch_bounds__(256) k_softmax(const float* __restrict__ gamma,
                                                 const float* __restrict__ beta) {
    __shared__ __half sT[64 * STS];
    __shared__ float sAsum[64];
    __shared__ float sSc[CC], sBi[CC];
    int tid = threadIdx.x, warp = tid >> 5, lane = tid & 31;
    int row0 = blockIdx.x * 128;
    int b = row0 >> 11, n0 = row0 & 2047;
    if (tid < 64) sAsum[tid] = 0.f;
    if (tid < CC) {
        float inv = 1.0f / (float)BN_TOT;
        float mean = g_colsum[tid] * inv;
        float var  = g_colsq[tid] * inv - mean * mean;
        float sc = rsqrtf(var + BN_EPS_F) * gamma[tid];
        sSc[tid] = sc;
        sBi[tid] = beta[tid] - mean * sc;
    }
    __syncthreads();
    float sc0 = sSc[lane],      bi0 = sBi[lane];
    float sc1 = sSc[lane + 32], bi1 = sBi[lane + 32];
    float sc2 = 0.f, bi2 = 0.f;
    if (lane < 16) { sc2 = sSc[lane + 64]; bi2 = sBi[lane + 64]; }
    float acc0 = 0.f, acc1 = 0.f;
    #pragma unroll
    for (int it = 0; it < 8; ++it) {
        int nlA = warp + it * 16, nlB = nlA + 8;
        const __half* pa = g_assn + (size_t)(row0 + nlA) * CC;
        const __half* pb = g_assn + (size_t)(row0 + nlB) * CC;
        float a0 = __half2float(pa[lane]) * sc0 + bi0;
        float b0 = __half2float(pb[lane]) * sc0 + bi0;
        float a1 = __half2float(pa[lane + 32]) * sc1 + bi1;
        float b1 = __half2float(pb[lane + 32]) * sc1 + bi1;
        float a2 = (lane < 16) ? (__half2float(pa[lane + 64]) * sc2 + bi2) : -1e30f;
        float b2 = (lane < 16) ? (__half2float(pb[lane + 64]) * sc2 + bi2) : -1e30f;
        float ma = fmaxf(fmaxf(a0, a1), a2);
        float mb = fmaxf(fmaxf(b0, b1), b2);
        #pragma unroll
        for (int o = 16; o; o >>= 1) {
            ma = fmaxf(ma, __shfl_xor_sync(0xffffffffu, ma, o));
            mb = fmaxf(mb, __shfl_xor_sync(0xffffffffu, mb, o));
        }
        float ea0 = __expf(a0 - ma), ea1 = __expf(a1 - ma);
        float eb0 = __expf(b0 - mb), eb1 = __expf(b1 - mb);
        float ea2 = (lane < 16) ? __expf(a2 - ma) : 0.f;
        float eb2 = (lane < 16) ? __expf(b2 - mb) : 0.f;
        float sa = ea0 + ea1 + ea2;
        float sb = eb0 + eb1 + eb2;
        #pragma unroll
        for (int o = 16; o; o >>= 1) {
            sa += __shfl_xor_sync(0xffffffffu, sa, o);
            sb += __shfl_xor_sync(0xffffffffu, sb, o);
        }
        float ia = 1.0f / sa, ib = 1.0f / sb;
        float pA0 = ea0 * ia, pA1 = ea1 * ia;
        float pB0 = eb0 * ib, pB1 = eb1 * ib;
        acc0 += pA0 + pB0; acc1 += pA1 + pB1;
        sT[lane * STS + nlA]        = __float2half(pA0);
        sT[(lane + 32) * STS + nlA] = __float2half(pA1);
        sT[lane * STS + nlB]        = __float2half(pB0);
        sT[(lane + 32) * STS + nlB] = __float2half(pB1);
    }
    atomicAdd(&sAsum[lane], acc0);
    atomicAdd(&sAsum[lane + 32], acc1);
    __syncthreads();
    int kc = tid >> 2, seg = tid & 3;
    size_t base = ((size_t)(b * KC + kc)) * NN + n0 + seg * 32;
    const __half* src = &sT[kc * STS + seg * 32];
    #pragma unroll
    for (int j = 0; j < 8; ++j)
        *(uint2*)&g_assnT[base + j * 4] = *(const uint2*)&src[j * 4];
    if (tid < 64) atomicAdd(&g_asum[b * KC + tid], sAsum[tid]);
}

// ---------------- kernel 3: vlad^T = assn^T @ x - a_sum*clusters2 — 3-STAGE PIPELINE ----------------
// grid 128 (32 b x 4 d-tiles of 128), 256 thr. n-chunks of 32, 3-stage cp.async, ONE sync/iter.
// smem = 3*(64+128)*40*2B = 45KB.
#define SAW 40   // 32 + 8 pad (halfs)
__global__ void __launch_bounds__(256, 2) k_gemm2(const float* __restrict__ clusters2) {
    __shared__ __align__(16) __half sA[3][64 * SAW];    // assnT tile [kc][n32]
    __shared__ __align__(16) __half sB[3][128 * SAW];   // xhT tile   [d][n32]
    int tid = threadIdx.x, warp = tid >> 5, lane = tid & 31;
    int g = lane >> 2, t = lane & 3;
    int b = blockIdx.x >> 2;
    int d0 = (blockIdx.x & 3) * 128;
    float acc[4][2][4] = {};
    const __half* Abase = g_assnT + (size_t)b * KC * NN;
    const __half* Bbase = g_xhT + ((size_t)b * DD + d0) * NN;

    const int a_r = tid >> 2, a_c = tid & 3;            // sA: 64 rows x 4 16B-chunks
    // prologue: issue stages 0 and 1 (group index == stage index)
    #pragma unroll
    for (int p = 0; p < 2; ++p) {
        cpasync16(&sA[p][a_r * SAW + a_c * 8], &Abase[(size_t)a_r * NN + p * 32 + a_c * 8]);
        #pragma unroll
        for (int it = 0; it < 2; ++it) {
            int id = it * 256 + tid; int r = id >> 2, c = id & 3;
            cpasync16(&sB[p][r * SAW + c * 8], &Bbase[(size_t)r * NN + p * 32 + c * 8]);
        }
        asm volatile("cp.async.commit_group;\n");
    }
    for (int s = 0; s < 64; ++s) {
        int buf = s % 3;
        if (s < 63) { asm volatile("cp.async.wait_group 1;\n"); }
        else        { asm volatile("cp.async.wait_group 0;\n"); }
        __syncthreads();   // stage s visible to all; all warps done reading stage s-1
        // issue stage s+2 into buffer (s+2)%3 == (s-1)%3 (reads finished before this sync)
        if (s + 2 < 64) {
            int nb = (s + 2) % 3, nn0 = (s + 2) * 32;
            cpasync16(&sA[nb][a_r * SAW + a_c * 8], &Abase[(size_t)a_r * NN + nn0 + a_c * 8]);
            #pragma unroll
            for (int it = 0; it < 2; ++it) {
                int id = it * 256 + tid; int r = id >> 2, c = id & 3;
                cpasync16(&sB[nb][r * SAW + c * 8], &Bbase[(size_t)r * NN + nn0 + c * 8]);
            }
            asm volatile("cp.async.commit_group;\n");
        }
        #pragma unroll
        for (int ks = 0; ks < 32; ks += 16) {
            uint32_t af[4][4], bf[2][2];
            #pragma unroll
            for (int mf = 0; mf < 4; ++mf) {
                const __half* base = &sA[buf][(mf * 16 + g) * SAW + ks + 2 * t];
                af[mf][0] = *(const uint32_t*)base;
                af[mf][1] = *(const uint32_t*)(base + 8 * SAW);
                af[mf][2] = *(const uint32_t*)(base + 8);
                af[mf][3] = *(const uint32_t*)(base + 8 * SAW + 8);
            }
            #pragma unroll
            for (int nf = 0; nf < 2; ++nf) {
                const __half* base = &sB[buf][(warp * 16 + nf * 8 + g) * SAW + ks + 2 * t];
                bf[nf][0] = *(const uint32_t*)base;
                bf[nf][1] = *(const uint32_t*)(base + 8);
            }
            #pragma unroll
            for (int mf = 0; mf < 4; ++mf)
                #pragma unroll
                for (int nf = 0; nf < 2; ++nf)
                    mma16816(acc[mf][nf], af[mf], bf[nf]);
        }
        // no second sync: next iteration's sync protects buffer reuse
    }
    // epilogue: subtract a_sum*clusters2, write vladT fp32, accumulate column sq-norms
    #pragma unroll
    for (int mf = 0; mf < 4; ++mf) {
        #pragma unroll
        for (int h = 0; h < 2; ++h) {
            int kc = mf * 16 + g + h * 8;
            float asv = g_asum[b * KC + kc];
            float nsq = 0.f;
            #pragma unroll
            for (int nf = 0; nf < 2; ++nf) {
                int d = d0 + warp * 16 + nf * 8 + 2 * t;
                float v0 = acc[mf][nf][h * 2 + 0] - asv * clusters2[(size_t)d * KC + kc];
                float v1 = acc[mf][nf][h * 2 + 1] - asv * clusters2[(size_t)(d + 1) * KC + kc];
                *(float2*)&g_vladT[((size_t)b * KC + kc) * DD + d] = make_float2(v0, v1);
                nsq += v0 * v0 + v1 * v1;
            }
            nsq += __shfl_xor_sync(0xffffffffu, nsq, 1);
            nsq += __shfl_xor_sync(0xffffffffu, nsq, 2);
            if (t == 0) atomicAdd(&g_colnorm[b * KC + kc], nsq);
        }
    }
}

// ---------------- kernel 4: (scales fused) + scale + transpose to out[b][d][k] ----------------
__global__ void __launch_bounds__(256) k_output(float* __restrict__ out) {
    __shared__ float sT[64][65];
    __shared__ float sR[64], sC[64];
    __shared__ float sTot;
    int tid = threadIdx.x;
    int b = blockIdx.x >> 3;
    int d0 = (blockIdx.x & 7) * 64;
    if (tid < 64) {
        float nsq = g_colnorm[b * KC + tid];
        float r = 1.0f / fmaxf(sqrtf(nsq), 1e-12f);
        sR[tid] = r;
        sC[tid] = nsq * r * r;   // ||col||^2 after intra-norm
    }
    __syncthreads();
    if (tid < 32) {
        float s = sC[tid] + sC[tid + 32];
        #pragma unroll
        for (int o = 16; o; o >>= 1) s += __shfl_xor_sync(0xffffffffu, s, o);
        if (tid == 0) sTot = s;
    }
    __syncthreads();
    float ginv = 1.0f / fmaxf(sqrtf(sTot), 1e-12f);
    {
        int kc = tid >> 2, seg = tid & 3;
        float s = sR[kc] * ginv;
        const float* src = &g_vladT[((size_t)b * KC + kc) * DD + d0 + seg * 16];
        #pragma unroll
        for (int j = 0; j < 4; ++j) {
            float4 v = *(const float4*)&src[j * 4];
            sT[kc][seg * 16 + j * 4 + 0] = v.x * s;
            sT[kc][seg * 16 + j * 4 + 1] = v.y * s;
            sT[kc][seg * 16 + j * 4 + 2] = v.z * s;
            sT[kc][seg * 16 + j * 4 + 3] = v.w * s;
        }
    }
    __syncthreads();
    {
        int d = tid >> 2, k0 = (tid & 3) * 16;
        float* dst = &out[(size_t)b * (DD * KC) + (size_t)(d0 + d) * KC + k0];
        #pragma unroll
        for (int j = 0; j < 4; ++j) {
            float4 v;
            v.x = sT[k0 + j * 4 + 0][d];
            v.y = sT[k0 + j * 4 + 1][d];
            v.z = sT[k0 + j * 4 + 2][d];
            v.w = sT[k0 + j * 4 + 3][d];
            *(float4*)&dst[j * 4] = v;
        }
    }
}

// ---------------- launch ----------------
extern "C" void kernel_launch(void* const* d_in, const int* in_sizes, int n_in,
                              void* d_out, int out_size) {
    (void)in_sizes; (void)n_in; (void)out_size;
    const float* x         = (const float*)d_in[0];
    const float* clusters  = (const float*)d_in[1];
    const float* clusters2 = (const float*)d_in[2];
    const float* gamma     = (const float*)d_in[3];
    const float* beta      = (const float*)d_in[4];
    float* out = (float*)d_out;

    k_init<<<64, 256>>>(clusters);
    k_gemm1<<<512, 256>>>(x);
    k_softmax<<<512, 256>>>(gamma, beta);
    k_gemm2<<<128, 256>>>(clusters2);
    k_output<<<256, 256>>>(out);
}

// round 14
// speedup vs baseline: 1.2608x; 1.2401x over previous
#include <cuda_runtime.h>
#include <cuda_fp16.h>
#include <cstdint>

#define BB 32
#define NN 2048
#define DD 512
#define KC 64
#define CC 80              // K + G
#define BN_TOT (BB*NN)     // 65536
#define BN_EPS_F 1e-5f

// ---------------- scratch (device globals; no allocation allowed) ----------------
__device__ __half g_assn[(size_t)BN_TOT * CC];        // raw assignments fp16 [row][80]
__device__ __half g_xh[(size_t)BN_TOT * DD];          // x fp16, NATURAL layout [row][d]
__device__ __half g_chT[CC * DD];                     // clusters^T fp16 [c][d]
__device__ __half g_assnT[(size_t)BB * KC * NN];      // softmaxed assn^T [b][k][n]
__device__ float  g_colsum[CC], g_colsq[CC];
__device__ float  g_asum[BB * KC];
__device__ float  g_vladT[(size_t)BB * KC * DD];      // vlad fp32 [b][k][d]
__device__ float  g_colnorm[BB * KC];

// ---------------- helpers ----------------
__device__ __forceinline__ void mma16816(float* c, const uint32_t* a, const uint32_t* b) {
    asm volatile(
        "mma.sync.aligned.m16n8k16.row.col.f32.f16.f16.f32 "
        "{%0,%1,%2,%3}, {%4,%5,%6,%7}, {%8,%9}, {%0,%1,%2,%3};\n"
        : "+f"(c[0]), "+f"(c[1]), "+f"(c[2]), "+f"(c[3])
        : "r"(a[0]), "r"(a[1]), "r"(a[2]), "r"(a[3]), "r"(b[0]), "r"(b[1]));
}
__device__ __forceinline__ uint32_t smemu32(const void* p) {
    return (uint32_t)__cvta_generic_to_shared(p);
}
__device__ __forceinline__ void cpasync16(void* smem, const void* g) {
    asm volatile("cp.async.cg.shared.global [%0], [%1], 16;\n"
                 :: "r"(smemu32(smem)), "l"(g));
}
__device__ __forceinline__ void ldsm_x4_t(uint32_t* r, uint32_t addr) {
    asm volatile("ldmatrix.sync.aligned.m8n8.x4.trans.shared.b16 {%0,%1,%2,%3}, [%4];\n"
                 : "=r"(r[0]), "=r"(r[1]), "=r"(r[2]), "=r"(r[3]) : "r"(addr));
}

// ---------------- kernel 0: zero accumulators + clusters^T to fp16 ----------------
__global__ void k_init(const float* __restrict__ clusters) {
    int tid = blockIdx.x * blockDim.x + threadIdx.x;
    if (tid < CC) { g_colsum[tid] = 0.f; g_colsq[tid] = 0.f; }
    if (tid < BB * KC) { g_asum[tid] = 0.f; g_colnorm[tid] = 0.f; }
    for (int i = tid; i < CC * DD; i += gridDim.x * blockDim.x) {
        int c = i / DD, d = i % DD;
        g_chT[i] = __float2half(clusters[d * CC + c]);
    }
}

// ---------------- kernel 1: assn = x @ clusters + xh(natural fp16) + FUSED column stats ----------------
// grid 512 x 256 thr. Block: 128 rows x 80 cols, K=512 in EIGHT chunks of 64. Pipelined.
// NO smem transpose: xh written straight from registers, coalesced.
__global__ void __launch_bounds__(256, 2) k_gemm1(const float* __restrict__ x) {
    __shared__ __align__(16) __half sA[128 * 72];
    __shared__ __align__(16) __half sB[80 * 72];
    __shared__ float sSum[CC], sSq[CC];
    const int tid = threadIdx.x;
    const int warp = tid >> 5, lane = tid & 31;
    const int g = lane >> 2, t = lane & 3;
    const int wm = warp >> 1, wn = warp & 1;
    const int row0 = blockIdx.x * 128;

    if (tid < CC) { sSum[tid] = 0.f; sSq[tid] = 0.f; }

    float acc[2][5][4] = {};

    // preload stage-0 x chunk into registers
    float4 rx[8];
    #pragma unroll
    for (int it = 0; it < 8; ++it) {
        int flat = (it * 256 + tid) * 4;
        int r = flat >> 6, c = flat & 63;
        rx[it] = *(const float4*)&x[(size_t)(row0 + r) * DD + c];
    }

    #pragma unroll
    for (int k0s = 0; k0s < 8; ++k0s) {          // 8 chunks × 64 = 512 = DD
        const int k0 = k0s * 64;
        // clusters^T tile via cp.async (80 rows x 64 halfs)
        #pragma unroll
        for (int it = 0; it < 3; ++it) {
            int id = it * 256 + tid;
            if (id < 640) {
                int c = id >> 3, c8 = id & 7;
                cpasync16(&sB[c * 72 + c8 * 8], &g_chT[c * DD + k0 + c8 * 8]);
            }
        }
        // convert + store A tile from registers; ALSO write xh fp16 natural (coalesced)
        #pragma unroll
        for (int it = 0; it < 8; ++it) {
            int flat = (it * 256 + tid) * 4;
            int r = flat >> 6, c = flat & 63;
            __half h[4];
            h[0] = __float2half(rx[it].x); h[1] = __float2half(rx[it].y);
            h[2] = __float2half(rx[it].z); h[3] = __float2half(rx[it].w);
            *(uint2*)&sA[r * 72 + c] = *(const uint2*)h;
            *(uint2*)&g_xh[(size_t)(row0 + r) * DD + k0 + c] = *(const uint2*)h;
        }
        asm volatile("cp.async.commit_group;\n");
        // prefetch next x chunk (overlaps mma below)
        if (k0s < 7) {
            #pragma unroll
            for (int it = 0; it < 8; ++it) {
                int flat = (it * 256 + tid) * 4;
                int r = flat >> 6, c = flat & 63;
                rx[it] = *(const float4*)&x[(size_t)(row0 + r) * DD + k0 + 64 + c];
            }
        }
        asm volatile("cp.async.wait_group 0;\n");
        __syncthreads();
        // mma over 4 k-steps of 16
        #pragma unroll
        for (int ks = 0; ks < 64; ks += 16) {
            uint32_t af[2][4], bf[5][2];
            #pragma unroll
            for (int mf = 0; mf < 2; ++mf) {
                const __half* base = &sA[(wm * 32 + mf * 16 + g) * 72 + ks + 2 * t];
                af[mf][0] = *(const uint32_t*)base;
                af[mf][1] = *(const uint32_t*)(base + 8 * 72);
                af[mf][2] = *(const uint32_t*)(base + 8);
                af[mf][3] = *(const uint32_t*)(base + 8 * 72 + 8);
            }
            #pragma unroll
            for (int nf = 0; nf < 5; ++nf) {
                const __half* base = &sB[(wn * 40 + nf * 8 + g) * 72 + ks + 2 * t];
                bf[nf][0] = *(const uint32_t*)base;
                bf[nf][1] = *(const uint32_t*)(base + 8);
            }
            #pragma unroll
            for (int mf = 0; mf < 2; ++mf)
                #pragma unroll
                for (int nf = 0; nf < 5; ++nf)
                    mma16816(acc[mf][nf], af[mf], bf[nf]);
        }
        __syncthreads();
    }
    // write raw assn (fp16)
    #pragma unroll
    for (int mf = 0; mf < 2; ++mf) {
        int r = row0 + wm * 32 + mf * 16 + g;
        #pragma unroll
        for (int nf = 0; nf < 5; ++nf) {
            int c = wn * 40 + nf * 8 + 2 * t;
            *(__half2*)&g_assn[(size_t)r * CC + c]       = __floats2half2_rn(acc[mf][nf][0], acc[mf][nf][1]);
            *(__half2*)&g_assn[(size_t)(r + 8) * CC + c] = __floats2half2_rn(acc[mf][nf][2], acc[mf][nf][3]);
        }
    }
    // FUSED column stats
    float ps[10], pq[10];
    #pragma unroll
    for (int nf = 0; nf < 5; ++nf)
        #pragma unroll
        for (int j = 0; j < 2; ++j) {
            float a0 = acc[0][nf][j], a1 = acc[0][nf][j + 2];
            float a2 = acc[1][nf][j], a3 = acc[1][nf][j + 2];
            ps[nf * 2 + j] = a0 + a1 + a2 + a3;
            pq[nf * 2 + j] = a0 * a0 + a1 * a1 + a2 * a2 + a3 * a3;
        }
    #pragma unroll
    for (int o = 16; o >= 4; o >>= 1)
        #pragma unroll
        for (int i = 0; i < 10; ++i) {
            ps[i] += __shfl_xor_sync(0xffffffffu, ps[i], o);
            pq[i] += __shfl_xor_sync(0xffffffffu, pq[i], o);
        }
    if (g == 0) {
        #pragma unroll
        for (int nf = 0; nf < 5; ++nf)
            #pragma unroll
            for (int j = 0; j < 2; ++j) {
                int c = wn * 40 + nf * 8 + 2 * t + j;
                atomicAdd(&sSum[c], ps[nf * 2 + j]);
                atomicAdd(&sSq[c],  pq[nf * 2 + j]);
            }
    }
    __syncthreads();
    if (tid < CC) {
        atomicAdd(&g_colsum[tid], sSum[tid]);
        atomicAdd(&g_colsq[tid],  sSq[tid]);
    }
}

// ---------------- kernel 2: (BN-finalize fused) + softmax + assn^T fp16 + a_sum ----------------
#define STS 132
__global__ void __launch_bounds__(256) k_softmax(const float* __restrict__ gamma,
                                                 const float* __restrict__ beta) {
    __shared__ __half sT[64 * STS];
    __shared__ float sAsum[64];
    __shared__ float sSc[CC], sBi[CC];
    int tid = threadIdx.x, warp = tid >> 5, lane = tid & 31;
    int row0 = blockIdx.x * 128;
    int b = row0 >> 11, n0 = row0 & 2047;
    if (tid < 64) sAsum[tid] = 0.f;
    if (tid < CC) {
        float inv = 1.0f / (float)BN_TOT;
        float mean = g_colsum[tid] * inv;
        float var  = g_colsq[tid] * inv - mean * mean;
        float sc = rsqrtf(var + BN_EPS_F) * gamma[tid];
        sSc[tid] = sc;
        sBi[tid] = beta[tid] - mean * sc;
    }
    __syncthreads();
    float sc0 = sSc[lane],      bi0 = sBi[lane];
    float sc1 = sSc[lane + 32], bi1 = sBi[lane + 32];
    float sc2 = 0.f, bi2 = 0.f;
    if (lane < 16) { sc2 = sSc[lane + 64]; bi2 = sBi[lane + 64]; }
    float acc0 = 0.f, acc1 = 0.f;
    #pragma unroll
    for (int it = 0; it < 8; ++it) {
        int nlA = warp + it * 16, nlB = nlA + 8;
        const __half* pa = g_assn + (size_t)(row0 + nlA) * CC;
        const __half* pb = g_assn + (size_t)(row0 + nlB) * CC;
        float a0 = __half2float(pa[lane]) * sc0 + bi0;
        float b0 = __half2float(pb[lane]) * sc0 + bi0;
        float a1 = __half2float(pa[lane + 32]) * sc1 + bi1;
        float b1 = __half2float(pb[lane + 32]) * sc1 + bi1;
        float a2 = (lane < 16) ? (__half2float(pa[lane + 64]) * sc2 + bi2) : -1e30f;
        float b2 = (lane < 16) ? (__half2float(pb[lane + 64]) * sc2 + bi2) : -1e30f;
        float ma = fmaxf(fmaxf(a0, a1), a2);
        float mb = fmaxf(fmaxf(b0, b1), b2);
        #pragma unroll
        for (int o = 16; o; o >>= 1) {
            ma = fmaxf(ma, __shfl_xor_sync(0xffffffffu, ma, o));
            mb = fmaxf(mb, __shfl_xor_sync(0xffffffffu, mb, o));
        }
        float ea0 = __expf(a0 - ma), ea1 = __expf(a1 - ma);
        float eb0 = __expf(b0 - mb), eb1 = __expf(b1 - mb);
        float ea2 = (lane < 16) ? __expf(a2 - ma) : 0.f;
        float eb2 = (lane < 16) ? __expf(b2 - mb) : 0.f;
        float sa = ea0 + ea1 + ea2;
        float sb = eb0 + eb1 + eb2;
        #pragma unroll
        for (int o = 16; o; o >>= 1) {
            sa += __shfl_xor_sync(0xffffffffu, sa, o);
            sb += __shfl_xor_sync(0xffffffffu, sb, o);
        }
        float ia = 1.0f / sa, ib = 1.0f / sb;
        float pA0 = ea0 * ia, pA1 = ea1 * ia;
        float pB0 = eb0 * ib, pB1 = eb1 * ib;
        acc0 += pA0 + pB0; acc1 += pA1 + pB1;
        sT[lane * STS + nlA]        = __float2half(pA0);
        sT[(lane + 32) * STS + nlA] = __float2half(pA1);
        sT[lane * STS + nlB]        = __float2half(pB0);
        sT[(lane + 32) * STS + nlB] = __float2half(pB1);
    }
    atomicAdd(&sAsum[lane], acc0);
    atomicAdd(&sAsum[lane + 32], acc1);
    __syncthreads();
    int kc = tid >> 2, seg = tid & 3;
    size_t base = ((size_t)(b * KC + kc)) * NN + n0 + seg * 32;
    const __half* src = &sT[kc * STS + seg * 32];
    #pragma unroll
    for (int j = 0; j < 8; ++j)
        *(uint2*)&g_assnT[base + j * 4] = *(const uint2*)&src[j * 4];
    if (tid < 64) atomicAdd(&g_asum[b * KC + tid], sAsum[tid]);
}

// ---------------- kernel 3: vlad^T = assn^T @ x - a_sum*clusters2 — 3-STAGE, ldsm.trans B ----------------
// grid 128 (32 b x 4 d-tiles of 128), 256 thr. n-chunks of 32, 3-stage cp.async, ONE sync/iter.
// B read from NATURAL-layout g_xh via ldmatrix.trans. smem = 3*(64*40 + 32*136)*2B = 40.5KB.
#define SAW 40    // assnT tile width: 32 + 8 pad (halfs)
#define SBW 136   // x tile width: 128 + 8 pad (halfs)
__global__ void __launch_bounds__(256, 2) k_gemm2(const float* __restrict__ clusters2) {
    __shared__ __align__(16) __half sA[3][64 * SAW];    // assnT tile [kc][n32]
    __shared__ __align__(16) __half sB[3][32 * SBW];    // x tile [n32][d128]
    int tid = threadIdx.x, warp = tid >> 5, lane = tid & 31;
    int g = lane >> 2, t = lane & 3;
    int b = blockIdx.x >> 2;
    int d0 = (blockIdx.x & 3) * 128;
    float acc[4][2][4] = {};
    const __half* Abase = g_assnT + (size_t)b * KC * NN;
    const __half* Bbase = g_xh + (size_t)b * NN * DD + d0;

    const int a_r = tid >> 2, a_c = tid & 3;            // sA: 64 rows x 4 16B-chunks
    const int lrow = lane & 15, lhi = (lane >> 4) * 8;  // ldsm.trans addressing
    // prologue: issue stages 0 and 1 (group index == stage index)
    #pragma unroll
    for (int p = 0; p < 2; ++p) {
        cpasync16(&sA[p][a_r * SAW + a_c * 8], &Abase[(size_t)a_r * NN + p * 32 + a_c * 8]);
        #pragma unroll
        for (int it = 0; it < 2; ++it) {
            int id = it * 256 + tid; int r = id >> 4, c = id & 15;
            cpasync16(&sB[p][r * SBW + c * 8], &Bbase[(size_t)(p * 32 + r) * DD + c * 8]);
        }
        asm volatile("cp.async.commit_group;\n");
    }
    for (int s = 0; s < 64; ++s) {
        int buf = s % 3;
        if (s < 63) { asm volatile("cp.async.wait_group 1;\n"); }
        else        { asm volatile("cp.async.wait_group 0;\n"); }
        __syncthreads();   // stage s visible; all warps done reading stage s-1
        if (s + 2 < 64) {
            int nb = (s + 2) % 3, nn0 = (s + 2) * 32;
            cpasync16(&sA[nb][a_r * SAW + a_c * 8], &Abase[(size_t)a_r * NN + nn0 + a_c * 8]);
            #pragma unroll
            for (int it = 0; it < 2; ++it) {
                int id = it * 256 + tid; int r = id >> 4, c = id & 15;
                cpasync16(&sB[nb][r * SBW + c * 8], &Bbase[(size_t)(nn0 + r) * DD + c * 8]);
            }
            asm volatile("cp.async.commit_group;\n");
        }
        #pragma unroll
        for (int ks = 0; ks < 32; ks += 16) {
            uint32_t af[4][4], bf[4];
            #pragma unroll
            for (int mf = 0; mf < 4; ++mf) {
                const __half* base = &sA[buf][(mf * 16 + g) * SAW + ks + 2 * t];
                af[mf][0] = *(const uint32_t*)base;
                af[mf][1] = *(const uint32_t*)(base + 8 * SAW);
                af[mf][2] = *(const uint32_t*)(base + 8);
                af[mf][3] = *(const uint32_t*)(base + 8 * SAW + 8);
            }
            ldsm_x4_t(bf, smemu32(&sB[buf][(ks + lrow) * SBW + warp * 16 + lhi]));
            #pragma unroll
            for (int mf = 0; mf < 4; ++mf) {
                mma16816(acc[mf][0], af[mf], &bf[0]);
                mma16816(acc[mf][1], af[mf], &bf[2]);
            }
        }
        // no second sync: next iteration's sync protects buffer reuse
    }
    // epilogue: subtract a_sum*clusters2, write vladT fp32, accumulate column sq-norms
    #pragma unroll
    for (int mf = 0; mf < 4; ++mf) {
        #pragma unroll
        for (int h = 0; h < 2; ++h) {
            int kc = mf * 16 + g + h * 8;
            float asv = g_asum[b * KC + kc];
            float nsq = 0.f;
            #pragma unroll
            for (int nf = 0; nf < 2; ++nf) {
                int d = d0 + warp * 16 + nf * 8 + 2 * t;
                float v0 = acc[mf][nf][h * 2 + 0] - asv * clusters2[(size_t)d * KC + kc];
                float v1 = acc[mf][nf][h * 2 + 1] - asv * clusters2[(size_t)(d + 1) * KC + kc];
                *(float2*)&g_vladT[((size_t)b * KC + kc) * DD + d] = make_float2(v0, v1);
                nsq += v0 * v0 + v1 * v1;
            }
            nsq += __shfl_xor_sync(0xffffffffu, nsq, 1);
            nsq += __shfl_xor_sync(0xffffffffu, nsq, 2);
            if (t == 0) atomicAdd(&g_colnorm[b * KC + kc], nsq);
        }
    }
}

// ---------------- kernel 4: (scales fused) + scale + transpose to out[b][d][k] ----------------
__global__ void __launch_bounds__(256) k_output(float* __restrict__ out) {
    __shared__ float sT[64][65];
    __shared__ float sR[64], sC[64];
    __shared__ float sTot;
    int tid = threadIdx.x;
    int b = blockIdx.x >> 3;
    int d0 = (blockIdx.x & 7) * 64;
    if (tid < 64) {
        float nsq = g_colnorm[b * KC + tid];
        float r = 1.0f / fmaxf(sqrtf(nsq), 1e-12f);
        sR[tid] = r;
        sC[tid] = nsq * r * r;   // ||col||^2 after intra-norm
    }
    __syncthreads();
    if (tid < 32) {
        float s = sC[tid] + sC[tid + 32];
        #pragma unroll
        for (int o = 16; o; o >>= 1) s += __shfl_xor_sync(0xffffffffu, s, o);
        if (tid == 0) sTot = s;
    }
    __syncthreads();
    float ginv = 1.0f / fmaxf(sqrtf(sTot), 1e-12f);
    {
        int kc = tid >> 2, seg = tid & 3;
        float s = sR[kc] * ginv;
        const float* src = &g_vladT[((size_t)b * KC + kc) * DD + d0 + seg * 16];
        #pragma unroll
        for (int j = 0; j < 4; ++j) {
            float4 v = *(const float4*)&src[j * 4];
            sT[kc][seg * 16 + j * 4 + 0] = v.x * s;
            sT[kc][seg * 16 + j * 4 + 1] = v.y * s;
            sT[kc][seg * 16 + j * 4 + 2] = v.z * s;
            sT[kc][seg * 16 + j * 4 + 3] = v.w * s;
        }
    }
    __syncthreads();
    {
        int d = tid >> 2, k0 = (tid & 3) * 16;
        float* dst = &out[(size_t)b * (DD * KC) + (size_t)(d0 + d) * KC + k0];
        #pragma unroll
        for (int j = 0; j < 4; ++j) {
            float4 v;
            v.x = sT[k0 + j * 4 + 0][d];
            v.y = sT[k0 + j * 4 + 1][d];
            v.z = sT[k0 + j * 4 + 2][d];
            v.w = sT[k0 + j * 4 + 3][d];
            *(float4*)&dst[j * 4] = v;
        }
    }
}

// ---------------- launch ----------------
extern "C" void kernel_launch(void* const* d_in, const int* in_sizes, int n_in,
                              void* d_out, int out_size) {
    (void)in_sizes; (void)n_in; (void)out_size;
    const float* x         = (const float*)d_in[0];
    const float* clusters  = (const float*)d_in[1];
    const float* clusters2 = (const float*)d_in[2];
    const float* gamma     = (const float*)d_in[3];
    const float* beta      = (const float*)d_in[4];
    float* out = (float*)d_out;

    k_init<<<64, 256>>>(clusters);
    k_gemm1<<<512, 256>>>(x);
    k_softmax<<<512, 256>>>(gamma, beta);
    k_gemm2<<<128, 256>>>(clusters2);
    k_output<<<256, 256>>>(out);
}

// round 16
// speedup vs baseline: 1.3083x; 1.0377x over previous
#include <cuda_runtime.h>
#include <cuda_fp16.h>
#include <cstdint>

#define BB 32
#define NN 2048
#define DD 512
#define KC 64
#define CC 80              // K + G
#define BN_TOT (BB*NN)     // 65536
#define BN_EPS_F 1e-5f

// ---------------- scratch (device globals; no allocation allowed) ----------------
__device__ __half g_assn[(size_t)BN_TOT * CC];        // raw assignments fp16 [row][80]
__device__ __half g_xh[(size_t)BN_TOT * DD];          // x fp16, NATURAL layout [row][d]
__device__ __half g_chT[CC * DD];                     // clusters^T fp16 [c][d]
__device__ __half g_assnT[(size_t)BB * KC * NN];      // softmaxed assn^T [b][k][n]
__device__ float  g_colsum[CC], g_colsq[CC];
__device__ float  g_asum[BB * KC];
__device__ float  g_vladT[(size_t)BB * KC * DD];      // vlad fp32 [b][k][d]
__device__ float  g_colnorm[BB * KC];

// ---------------- helpers ----------------
__device__ __forceinline__ void mma16816(float* c, const uint32_t* a, const uint32_t* b) {
    asm volatile(
        "mma.sync.aligned.m16n8k16.row.col.f32.f16.f16.f32 "
        "{%0,%1,%2,%3}, {%4,%5,%6,%7}, {%8,%9}, {%0,%1,%2,%3};\n"
        : "+f"(c[0]), "+f"(c[1]), "+f"(c[2]), "+f"(c[3])
        : "r"(a[0]), "r"(a[1]), "r"(a[2]), "r"(a[3]), "r"(b[0]), "r"(b[1]));
}
__device__ __forceinline__ uint32_t smemu32(const void* p) {
    return (uint32_t)__cvta_generic_to_shared(p);
}
__device__ __forceinline__ void cpasync16(void* smem, const void* g) {
    asm volatile("cp.async.cg.shared.global [%0], [%1], 16;\n"
                 :: "r"(smemu32(smem)), "l"(g));
}
__device__ __forceinline__ void ldsm_x4_t(uint32_t* r, uint32_t addr) {
    asm volatile("ldmatrix.sync.aligned.m8n8.x4.trans.shared.b16 {%0,%1,%2,%3}, [%4];\n"
                 : "=r"(r[0]), "=r"(r[1]), "=r"(r[2]), "=r"(r[3]) : "r"(addr));
}

// ---------------- kernel 0: zero accumulators + clusters^T to fp16 ----------------
__global__ void k_init(const float* __restrict__ clusters) {
    int tid = blockIdx.x * blockDim.x + threadIdx.x;
    if (tid < CC) { g_colsum[tid] = 0.f; g_colsq[tid] = 0.f; }
    if (tid < BB * KC) { g_asum[tid] = 0.f; g_colnorm[tid] = 0.f; }
    for (int i = tid; i < CC * DD; i += gridDim.x * blockDim.x) {
        int c = i / DD, d = i % DD;
        g_chT[i] = __float2half(clusters[d * CC + c]);
    }
}

// ---------------- kernel 1: assn = x @ clusters + xh(natural fp16) + FUSED column stats ----------------
// grid 512 x 256 thr. Block: 128 rows x 80 cols, K=512 in EIGHT chunks of 64. Pipelined.
__global__ void __launch_bounds__(256, 2) k_gemm1(const float* __restrict__ x) {
    __shared__ __align__(16) __half sA[128 * 72];
    __shared__ __align__(16) __half sB[80 * 72];
    __shared__ float sSum[CC], sSq[CC];
    const int tid = threadIdx.x;
    const int warp = tid >> 5, lane = tid & 31;
    const int g = lane >> 2, t = lane & 3;
    const int wm = warp >> 1, wn = warp & 1;
    const int row0 = blockIdx.x * 128;

    if (tid < CC) { sSum[tid] = 0.f; sSq[tid] = 0.f; }

    float acc[2][5][4] = {};

    // preload stage-0 x chunk into registers
    float4 rx[8];
    #pragma unroll
    for (int it = 0; it < 8; ++it) {
        int flat = (it * 256 + tid) * 4;
        int r = flat >> 6, c = flat & 63;
        rx[it] = *(const float4*)&x[(size_t)(row0 + r) * DD + c];
    }

    #pragma unroll
    for (int k0s = 0; k0s < 8; ++k0s) {          // 8 chunks × 64 = 512 = DD
        const int k0 = k0s * 64;
        #pragma unroll
        for (int it = 0; it < 3; ++it) {
            int id = it * 256 + tid;
            if (id < 640) {
                int c = id >> 3, c8 = id & 7;
                cpasync16(&sB[c * 72 + c8 * 8], &g_chT[c * DD + k0 + c8 * 8]);
            }
        }
        // convert + store A tile from registers; ALSO write xh fp16 natural (coalesced)
        #pragma unroll
        for (int it = 0; it < 8; ++it) {
            int flat = (it * 256 + tid) * 4;
            int r = flat >> 6, c = flat & 63;
            __half h[4];
            h[0] = __float2half(rx[it].x); h[1] = __float2half(rx[it].y);
            h[2] = __float2half(rx[it].z); h[3] = __float2half(rx[it].w);
            *(uint2*)&sA[r * 72 + c] = *(const uint2*)h;
            *(uint2*)&g_xh[(size_t)(row0 + r) * DD + k0 + c] = *(const uint2*)h;
        }
        asm volatile("cp.async.commit_group;\n");
        if (k0s < 7) {
            #pragma unroll
            for (int it = 0; it < 8; ++it) {
                int flat = (it * 256 + tid) * 4;
                int r = flat >> 6, c = flat & 63;
                rx[it] = *(const float4*)&x[(size_t)(row0 + r) * DD + k0 + 64 + c];
            }
        }
        asm volatile("cp.async.wait_group 0;\n");
        __syncthreads();
        #pragma unroll
        for (int ks = 0; ks < 64; ks += 16) {
            uint32_t af[2][4], bf[5][2];
            #pragma unroll
            for (int mf = 0; mf < 2; ++mf) {
                const __half* base = &sA[(wm * 32 + mf * 16 + g) * 72 + ks + 2 * t];
                af[mf][0] = *(const uint32_t*)base;
                af[mf][1] = *(const uint32_t*)(base + 8 * 72);
                af[mf][2] = *(const uint32_t*)(base + 8);
                af[mf][3] = *(const uint32_t*)(base + 8 * 72 + 8);
            }
            #pragma unroll
            for (int nf = 0; nf < 5; ++nf) {
                const __half* base = &sB[(wn * 40 + nf * 8 + g) * 72 + ks + 2 * t];
                bf[nf][0] = *(const uint32_t*)base;
                bf[nf][1] = *(const uint32_t*)(base + 8);
            }
            #pragma unroll
            for (int mf = 0; mf < 2; ++mf)
                #pragma unroll
                for (int nf = 0; nf < 5; ++nf)
                    mma16816(acc[mf][nf], af[mf], bf[nf]);
        }
        __syncthreads();
    }
    // write raw assn (fp16)
    #pragma unroll
    for (int mf = 0; mf < 2; ++mf) {
        int r = row0 + wm * 32 + mf * 16 + g;
        #pragma unroll
        for (int nf = 0; nf < 5; ++nf) {
            int c = wn * 40 + nf * 8 + 2 * t;
            *(__half2*)&g_assn[(size_t)r * CC + c]       = __floats2half2_rn(acc[mf][nf][0], acc[mf][nf][1]);
            *(__half2*)&g_assn[(size_t)(r + 8) * CC + c] = __floats2half2_rn(acc[mf][nf][2], acc[mf][nf][3]);
        }
    }
    // FUSED column stats
    float ps[10], pq[10];
    #pragma unroll
    for (int nf = 0; nf < 5; ++nf)
        #pragma unroll
        for (int j = 0; j < 2; ++j) {
            float a0 = acc[0][nf][j], a1 = acc[0][nf][j + 2];
            float a2 = acc[1][nf][j], a3 = acc[1][nf][j + 2];
            ps[nf * 2 + j] = a0 + a1 + a2 + a3;
            pq[nf * 2 + j] = a0 * a0 + a1 * a1 + a2 * a2 + a3 * a3;
        }
    #pragma unroll
    for (int o = 16; o >= 4; o >>= 1)
        #pragma unroll
        for (int i = 0; i < 10; ++i) {
            ps[i] += __shfl_xor_sync(0xffffffffu, ps[i], o);
            pq[i] += __shfl_xor_sync(0xffffffffu, pq[i], o);
        }
    if (g == 0) {
        #pragma unroll
        for (int nf = 0; nf < 5; ++nf)
            #pragma unroll
            for (int j = 0; j < 2; ++j) {
                int c = wn * 40 + nf * 8 + 2 * t + j;
                atomicAdd(&sSum[c], ps[nf * 2 + j]);
                atomicAdd(&sSq[c],  pq[nf * 2 + j]);
            }
    }
    __syncthreads();
    if (tid < CC) {
        atomicAdd(&g_colsum[tid], sSum[tid]);
        atomicAdd(&g_colsq[tid],  sSq[tid]);
    }
}

// ---------------- kernel 2: (BN-finalize fused) + softmax + assn^T fp16 + a_sum ----------------
#define STS 132
__global__ void __launch_bounds__(256) k_softmax(const float* __restrict__ gamma,
                                                 const float* __restrict__ beta) {
    __shared__ __half sT[64 * STS];
    __shared__ float sAsum[64];
    __shared__ float sSc[CC], sBi[CC];
    int tid = threadIdx.x, warp = tid >> 5, lane = tid & 31;
    int row0 = blockIdx.x * 128;
    int b = row0 >> 11, n0 = row0 & 2047;
    if (tid < 64) sAsum[tid] = 0.f;
    if (tid < CC) {
        float inv = 1.0f / (float)BN_TOT;
        float mean = g_colsum[tid] * inv;
        float var  = g_colsq[tid] * inv - mean * mean;
        float sc = rsqrtf(var + BN_EPS_F) * gamma[tid];
        sSc[tid] = sc;
        sBi[tid] = beta[tid] - mean * sc;
    }
    __syncthreads();
    float sc0 = sSc[lane],      bi0 = sBi[lane];
    float sc1 = sSc[lane + 32], bi1 = sBi[lane + 32];
    float sc2 = 0.f, bi2 = 0.f;
    if (lane < 16) { sc2 = sSc[lane + 64]; bi2 = sBi[lane + 64]; }
    float acc0 = 0.f, acc1 = 0.f;
    #pragma unroll
    for (int it = 0; it < 8; ++it) {
        int nlA = warp + it * 16, nlB = nlA + 8;
        const __half* pa = g_assn + (size_t)(row0 + nlA) * CC;
        const __half* pb = g_assn + (size_t)(row0 + nlB) * CC;
        float a0 = __half2float(pa[lane]) * sc0 + bi0;
        float b0 = __half2float(pb[lane]) * sc0 + bi0;
        float a1 = __half2float(pa[lane + 32]) * sc1 + bi1;
        float b1 = __half2float(pb[lane + 32]) * sc1 + bi1;
        float a2 = (lane < 16) ? (__half2float(pa[lane + 64]) * sc2 + bi2) : -1e30f;
        float b2 = (lane < 16) ? (__half2float(pb[lane + 64]) * sc2 + bi2) : -1e30f;
        float ma = fmaxf(fmaxf(a0, a1), a2);
        float mb = fmaxf(fmaxf(b0, b1), b2);
        #pragma unroll
        for (int o = 16; o; o >>= 1) {
            ma = fmaxf(ma, __shfl_xor_sync(0xffffffffu, ma, o));
            mb = fmaxf(mb, __shfl_xor_sync(0xffffffffu, mb, o));
        }
        float ea0 = __expf(a0 - ma), ea1 = __expf(a1 - ma);
        float eb0 = __expf(b0 - mb), eb1 = __expf(b1 - mb);
        float ea2 = (lane < 16) ? __expf(a2 - ma) : 0.f;
        float eb2 = (lane < 16) ? __expf(b2 - mb) : 0.f;
        float sa = ea0 + ea1 + ea2;
        float sb = eb0 + eb1 + eb2;
        #pragma unroll
        for (int o = 16; o; o >>= 1) {
            sa += __shfl_xor_sync(0xffffffffu, sa, o);
            sb += __shfl_xor_sync(0xffffffffu, sb, o);
        }
        float ia = 1.0f / sa, ib = 1.0f / sb;
        float pA0 = ea0 * ia, pA1 = ea1 * ia;
        float pB0 = eb0 * ib, pB1 = eb1 * ib;
        acc0 += pA0 + pB0; acc1 += pA1 + pB1;
        sT[lane * STS + nlA]        = __float2half(pA0);
        sT[(lane + 32) * STS + nlA] = __float2half(pA1);
        sT[lane * STS + nlB]        = __float2half(pB0);
        sT[(lane + 32) * STS + nlB] = __float2half(pB1);
    }
    atomicAdd(&sAsum[lane], acc0);
    atomicAdd(&sAsum[lane + 32], acc1);
    __syncthreads();
    int kc = tid >> 2, seg = tid & 3;
    size_t base = ((size_t)(b * KC + kc)) * NN + n0 + seg * 32;
    const __half* src = &sT[kc * STS + seg * 32];
    #pragma unroll
    for (int j = 0; j < 8; ++j)
        *(uint2*)&g_assnT[base + j * 4] = *(const uint2*)&src[j * 4];
    if (tid < 64) atomicAdd(&g_asum[b * KC + tid], sAsum[tid]);
}

// ---------------- kernel 3: vlad^T = assn^T @ x - a_sum*clusters2 — 4-STAGE, d-tile 64 ----------------
// grid 256 (32 b x 8 d-tiles of 64), 256 thr. n-chunks of 32, 4-stage cp.async, ONE sync/iter.
// Warp mapping: wk=warp>>2 takes k-half (32 rows), wd=warp&3 takes 16 d.
// smem = 4*(64*40 + 32*72)*2B = 38.9KB.
#define SAW 40    // assnT tile width: 32 + 8 pad (halfs); row stride 80B (16B-aligned)
#define SBW 72    // x tile width: 64 + 8 pad (halfs); row stride 144B (16B-aligned)
__global__ void __launch_bounds__(256, 2) k_gemm2(const float* __restrict__ clusters2) {
    __shared__ __align__(16) __half sA[4][64 * SAW];    // assnT tile [kc][n32]
    __shared__ __align__(16) __half sB[4][32 * SBW];    // x tile [n32][d64]
    int tid = threadIdx.x, warp = tid >> 5, lane = tid & 31;
    int g = lane >> 2, t = lane & 3;
    int wk = warp >> 2, wd = warp & 3;
    int b = blockIdx.x >> 3;
    int d0 = (blockIdx.x & 7) * 64;
    float acc[2][2][4] = {};
    const __half* Abase = g_assnT + (size_t)b * KC * NN;
    const __half* Bbase = g_xh + (size_t)b * NN * DD + d0;

    const int a_r = tid >> 2, a_c = tid & 3;            // sA: 64 rows x 4 16B-chunks
    const int b_r = tid >> 3, b_c = tid & 7;            // sB: 32 rows x 8 16B-chunks
    const int lrow = lane & 15, lhi = (lane >> 4) * 8;  // ldsm.trans addressing
    // prologue: issue stages 0,1,2 (group index == stage index)
    #pragma unroll
    for (int p = 0; p < 3; ++p) {
        cpasync16(&sA[p][a_r * SAW + a_c * 8], &Abase[(size_t)a_r * NN + p * 32 + a_c * 8]);
        cpasync16(&sB[p][b_r * SBW + b_c * 8], &Bbase[(size_t)(p * 32 + b_r) * DD + b_c * 8]);
        asm volatile("cp.async.commit_group;\n");
    }
    for (int s = 0; s < 64; ++s) {
        int buf = s & 3;
        if (s <= 61)      { asm volatile("cp.async.wait_group 2;\n"); }
        else if (s == 62) { asm volatile("cp.async.wait_group 1;\n"); }
        else              { asm volatile("cp.async.wait_group 0;\n"); }
        __syncthreads();   // stage s visible; all warps done reading stage s-1
        if (s + 3 < 64) {
            int nb = (s + 3) & 3, nn0 = (s + 3) * 32;   // (s+3)%4 == (s-1)%4: reads finished
            cpasync16(&sA[nb][a_r * SAW + a_c * 8], &Abase[(size_t)a_r * NN + nn0 + a_c * 8]);
            cpasync16(&sB[nb][b_r * SBW + b_c * 8], &Bbase[(size_t)(nn0 + b_r) * DD + b_c * 8]);
            asm volatile("cp.async.commit_group;\n");
        }
        #pragma unroll
        for (int ks = 0; ks < 32; ks += 16) {
            uint32_t af[2][4], bf[4];
            #pragma unroll
            for (int mf = 0; mf < 2; ++mf) {
                const __half* base = &sA[buf][(wk * 32 + mf * 16 + g) * SAW + ks + 2 * t];
                af[mf][0] = *(const uint32_t*)base;
                af[mf][1] = *(const uint32_t*)(base + 8 * SAW);
                af[mf][2] = *(const uint32_t*)(base + 8);
                af[mf][3] = *(const uint32_t*)(base + 8 * SAW + 8);
            }
            ldsm_x4_t(bf, smemu32(&sB[buf][(ks + lrow) * SBW + wd * 16 + lhi]));
            #pragma unroll
            for (int mf = 0; mf < 2; ++mf) {
                mma16816(acc[mf][0], af[mf], &bf[0]);
                mma16816(acc[mf][1], af[mf], &bf[2]);
            }
        }
        // no second sync: next iteration's sync protects buffer reuse
    }
    // epilogue: subtract a_sum*clusters2, write vladT fp32, accumulate column sq-norms
    #pragma unroll
    for (int mf = 0; mf < 2; ++mf) {
        #pragma unroll
        for (int h = 0; h < 2; ++h) {
            int kc = wk * 32 + mf * 16 + g + h * 8;
            float asv = g_asum[b * KC + kc];
            float nsq = 0.f;
            #pragma unroll
            for (int nf = 0; nf < 2; ++nf) {
                int d = d0 + wd * 16 + nf * 8 + 2 * t;
                float v0 = acc[mf][nf][h * 2 + 0] - asv * clusters2[(size_t)d * KC + kc];
                float v1 = acc[mf][nf][h * 2 + 1] - asv * clusters2[(size_t)(d + 1) * KC + kc];
                *(float2*)&g_vladT[((size_t)b * KC + kc) * DD + d] = make_float2(v0, v1);
                nsq += v0 * v0 + v1 * v1;
            }
            nsq += __shfl_xor_sync(0xffffffffu, nsq, 1);
            nsq += __shfl_xor_sync(0xffffffffu, nsq, 2);
            if (t == 0) atomicAdd(&g_colnorm[b * KC + kc], nsq);
        }
    }
}

// ---------------- kernel 4: (scales fused) + scale + transpose to out[b][d][k] ----------------
__global__ void __launch_bounds__(256) k_output(float* __restrict__ out) {
    __shared__ float sT[64][65];
    __shared__ float sR[64], sC[64];
    __shared__ float sTot;
    int tid = threadIdx.x;
    int b = blockIdx.x >> 3;
    int d0 = (blockIdx.x & 7) * 64;
    if (tid < 64) {
        float nsq = g_colnorm[b * KC + tid];
        float r = 1.0f / fmaxf(sqrtf(nsq), 1e-12f);
        sR[tid] = r;
        sC[tid] = nsq * r * r;   // ||col||^2 after intra-norm
    }
    __syncthreads();
    if (tid < 32) {
        float s = sC[tid] + sC[tid + 32];
        #pragma unroll
        for (int o = 16; o; o >>= 1) s += __shfl_xor_sync(0xffffffffu, s, o);
        if (tid == 0) sTot = s;
    }
    __syncthreads();
    float ginv = 1.0f / fmaxf(sqrtf(sTot), 1e-12f);
    {
        int kc = tid >> 2, seg = tid & 3;
        float s = sR[kc] * ginv;
        const float* src = &g_vladT[((size_t)b * KC + kc) * DD + d0 + seg * 16];
        #pragma unroll
        for (int j = 0; j < 4; ++j) {
            float4 v = *(const float4*)&src[j * 4];
            sT[kc][seg * 16 + j * 4 + 0] = v.x * s;
            sT[kc][seg * 16 + j * 4 + 1] = v.y * s;
            sT[kc][seg * 16 + j * 4 + 2] = v.z * s;
            sT[kc][seg * 16 + j * 4 + 3] = v.w * s;
        }
    }
    __syncthreads();
    {
        int d = tid >> 2, k0 = (tid & 3) * 16;
        float* dst = &out[(size_t)b * (DD * KC) + (size_t)(d0 + d) * KC + k0];
        #pragma unroll
        for (int j = 0; j < 4; ++j) {
            float4 v;
            v.x = sT[k0 + j * 4 + 0][d];
            v.y = sT[k0 + j * 4 + 1][d];
            v.z = sT[k0 + j * 4 + 2][d];
            v.w = sT[k0 + j * 4 + 3][d];
            *(float4*)&dst[j * 4] = v;
        }
    }
}

// ---------------- launch ----------------
extern "C" void kernel_launch(void* const* d_in, const int* in_sizes, int n_in,
                              void* d_out, int out_size) {
    (void)in_sizes; (void)n_in; (void)out_size;
    const float* x         = (const float*)d_in[0];
    const float* clusters  = (const float*)d_in[1];
    const float* clusters2 = (const float*)d_in[2];
    const float* gamma     = (const float*)d_in[3];
    const float* beta      = (const float*)d_in[4];
    float* out = (float*)d_out;

    k_init<<<64, 256>>>(clusters);
    k_gemm1<<<512, 256>>>(x);
    k_softmax<<<512, 256>>>(gamma, beta);
    k_gemm2<<<256, 256>>>(clusters2);
    k_output<<<256, 256>>>(out);
}

// round 17
// speedup vs baseline: 1.3375x; 1.0223x over previous
#include <cuda_runtime.h>
#include <cuda_fp16.h>
#include <cstdint>

#define BB 32
#define NN 2048
#define DD 512
#define KC 64
#define CC 80              // K + G
#define BN_TOT (BB*NN)     // 65536
#define BN_EPS_F 1e-5f

// ---------------- scratch (device globals; no allocation allowed) ----------------
__device__ __half g_assn[(size_t)BN_TOT * CC];        // raw assignments fp16 [row][80]
__device__ __half g_xh[(size_t)BN_TOT * DD];          // x fp16, NATURAL layout [row][d]
__device__ __half g_chT[CC * DD];                     // clusters^T fp16 [c][d]
__device__ __half g_assnT[(size_t)BB * KC * NN];      // softmaxed assn^T [b][k][n]
__device__ float  g_colsum[CC], g_colsq[CC];
__device__ float  g_asum[BB * KC];
__device__ float  g_vladT[(size_t)BB * KC * DD];      // vlad fp32 [b][k][d]
__device__ float  g_colnorm[BB * KC];

// ---------------- helpers ----------------
__device__ __forceinline__ void mma16816(float* c, const uint32_t* a, const uint32_t* b) {
    asm volatile(
        "mma.sync.aligned.m16n8k16.row.col.f32.f16.f16.f32 "
        "{%0,%1,%2,%3}, {%4,%5,%6,%7}, {%8,%9}, {%0,%1,%2,%3};\n"
        : "+f"(c[0]), "+f"(c[1]), "+f"(c[2]), "+f"(c[3])
        : "r"(a[0]), "r"(a[1]), "r"(a[2]), "r"(a[3]), "r"(b[0]), "r"(b[1]));
}
__device__ __forceinline__ uint32_t smemu32(const void* p) {
    return (uint32_t)__cvta_generic_to_shared(p);
}
__device__ __forceinline__ void cpasync16(void* smem, const void* g) {
    asm volatile("cp.async.cg.shared.global [%0], [%1], 16;\n"
                 :: "r"(smemu32(smem)), "l"(g));
}
__device__ __forceinline__ void ldsm_x4(uint32_t* r, uint32_t addr) {
    asm volatile("ldmatrix.sync.aligned.m8n8.x4.shared.b16 {%0,%1,%2,%3}, [%4];\n"
                 : "=r"(r[0]), "=r"(r[1]), "=r"(r[2]), "=r"(r[3]) : "r"(addr));
}
__device__ __forceinline__ void ldsm_x4_t(uint32_t* r, uint32_t addr) {
    asm volatile("ldmatrix.sync.aligned.m8n8.x4.trans.shared.b16 {%0,%1,%2,%3}, [%4];\n"
                 : "=r"(r[0]), "=r"(r[1]), "=r"(r[2]), "=r"(r[3]) : "r"(addr));
}

// ---------------- kernel 0: zero accumulators + clusters^T to fp16 ----------------
__global__ void k_init(const float* __restrict__ clusters) {
    int tid = blockIdx.x * blockDim.x + threadIdx.x;
    if (tid < CC) { g_colsum[tid] = 0.f; g_colsq[tid] = 0.f; }
    if (tid < BB * KC) { g_asum[tid] = 0.f; g_colnorm[tid] = 0.f; }
    for (int i = tid; i < CC * DD; i += gridDim.x * blockDim.x) {
        int c = i / DD, d = i % DD;
        g_chT[i] = __float2half(clusters[d * CC + c]);
    }
}

// ---------------- kernel 1: assn = x @ clusters + xh(natural fp16) + FUSED column stats ----------------
// grid 512 x 256 thr. Block: 128 rows x 80 cols, K=512 in EIGHT chunks of 64. Pipelined.
__global__ void __launch_bounds__(256, 2) k_gemm1(const float* __restrict__ x) {
    __shared__ __align__(16) __half sA[128 * 72];
    __shared__ __align__(16) __half sB[80 * 72];
    __shared__ float sSum[CC], sSq[CC];
    const int tid = threadIdx.x;
    const int warp = tid >> 5, lane = tid & 31;
    const int g = lane >> 2, t = lane & 3;
    const int wm = warp >> 1, wn = warp & 1;
    const int row0 = blockIdx.x * 128;

    if (tid < CC) { sSum[tid] = 0.f; sSq[tid] = 0.f; }

    float acc[2][5][4] = {};

    // preload stage-0 x chunk into registers
    float4 rx[8];
    #pragma unroll
    for (int it = 0; it < 8; ++it) {
        int flat = (it * 256 + tid) * 4;
        int r = flat >> 6, c = flat & 63;
        rx[it] = *(const float4*)&x[(size_t)(row0 + r) * DD + c];
    }

    #pragma unroll
    for (int k0s = 0; k0s < 8; ++k0s) {          // 8 chunks × 64 = 512 = DD
        const int k0 = k0s * 64;
        #pragma unroll
        for (int it = 0; it < 3; ++it) {
            int id = it * 256 + tid;
            if (id < 640) {
                int c = id >> 3, c8 = id & 7;
                cpasync16(&sB[c * 72 + c8 * 8], &g_chT[c * DD + k0 + c8 * 8]);
            }
        }
        // convert + store A tile from registers; ALSO write xh fp16 natural (coalesced)
        #pragma unroll
        for (int it = 0; it < 8; ++it) {
            int flat = (it * 256 + tid) * 4;
            int r = flat >> 6, c = flat & 63;
            __half h[4];
            h[0] = __float2half(rx[it].x); h[1] = __float2half(rx[it].y);
            h[2] = __float2half(rx[it].z); h[3] = __float2half(rx[it].w);
            *(uint2*)&sA[r * 72 + c] = *(const uint2*)h;
            *(uint2*)&g_xh[(size_t)(row0 + r) * DD + k0 + c] = *(const uint2*)h;
        }
        asm volatile("cp.async.commit_group;\n");
        if (k0s < 7) {
            #pragma unroll
            for (int it = 0; it < 8; ++it) {
                int flat = (it * 256 + tid) * 4;
                int r = flat >> 6, c = flat & 63;
                rx[it] = *(const float4*)&x[(size_t)(row0 + r) * DD + k0 + 64 + c];
            }
        }
        asm volatile("cp.async.wait_group 0;\n");
        __syncthreads();
        #pragma unroll
        for (int ks = 0; ks < 64; ks += 16) {
            uint32_t af[2][4], bf[5][2];
            #pragma unroll
            for (int mf = 0; mf < 2; ++mf) {
                const __half* base = &sA[(wm * 32 + mf * 16 + g) * 72 + ks + 2 * t];
                af[mf][0] = *(const uint32_t*)base;
                af[mf][1] = *(const uint32_t*)(base + 8 * 72);
                af[mf][2] = *(const uint32_t*)(base + 8);
                af[mf][3] = *(const uint32_t*)(base + 8 * 72 + 8);
            }
            #pragma unroll
            for (int nf = 0; nf < 5; ++nf) {
                const __half* base = &sB[(wn * 40 + nf * 8 + g) * 72 + ks + 2 * t];
                bf[nf][0] = *(const uint32_t*)base;
                bf[nf][1] = *(const uint32_t*)(base + 8);
            }
            #pragma unroll
            for (int mf = 0; mf < 2; ++mf)
                #pragma unroll
                for (int nf = 0; nf < 5; ++nf)
                    mma16816(acc[mf][nf], af[mf], bf[nf]);
        }
        __syncthreads();
    }
    // write raw assn (fp16)
    #pragma unroll
    for (int mf = 0; mf < 2; ++mf) {
        int r = row0 + wm * 32 + mf * 16 + g;
        #pragma unroll
        for (int nf = 0; nf < 5; ++nf) {
            int c = wn * 40 + nf * 8 + 2 * t;
            *(__half2*)&g_assn[(size_t)r * CC + c]       = __floats2half2_rn(acc[mf][nf][0], acc[mf][nf][1]);
            *(__half2*)&g_assn[(size_t)(r + 8) * CC + c] = __floats2half2_rn(acc[mf][nf][2], acc[mf][nf][3]);
        }
    }
    // FUSED column stats
    float ps[10], pq[10];
    #pragma unroll
    for (int nf = 0; nf < 5; ++nf)
        #pragma unroll
        for (int j = 0; j < 2; ++j) {
            float a0 = acc[0][nf][j], a1 = acc[0][nf][j + 2];
            float a2 = acc[1][nf][j], a3 = acc[1][nf][j + 2];
            ps[nf * 2 + j] = a0 + a1 + a2 + a3;
            pq[nf * 2 + j] = a0 * a0 + a1 * a1 + a2 * a2 + a3 * a3;
        }
    #pragma unroll
    for (int o = 16; o >= 4; o >>= 1)
        #pragma unroll
        for (int i = 0; i < 10; ++i) {
            ps[i] += __shfl_xor_sync(0xffffffffu, ps[i], o);
            pq[i] += __shfl_xor_sync(0xffffffffu, pq[i], o);
        }
    if (g == 0) {
        #pragma unroll
        for (int nf = 0; nf < 5; ++nf)
            #pragma unroll
            for (int j = 0; j < 2; ++j) {
                int c = wn * 40 + nf * 8 + 2 * t + j;
                atomicAdd(&sSum[c], ps[nf * 2 + j]);
                atomicAdd(&sSq[c],  pq[nf * 2 + j]);
            }
    }
    __syncthreads();
    if (tid < CC) {
        atomicAdd(&g_colsum[tid], sSum[tid]);
        atomicAdd(&g_colsq[tid],  sSq[tid]);
    }
}

// ---------------- kernel 2: (BN-finalize fused) + softmax (no max-shift) + assn^T fp16 + a_sum ----------------
// BN output is variance-normalized (|v| <~ 6 << 88), so exp() without max-subtraction is safe
// and softmax is shift-invariant -> identical result, half the shuffle-reduction chains.
#define STS 132
__global__ void __launch_bounds__(256) k_softmax(const float* __restrict__ gamma,
                                                 const float* __restrict__ beta) {
    __shared__ __half sT[64 * STS];
    __shared__ float sAsum[64];
    __shared__ float sSc[CC], sBi[CC];
    int tid = threadIdx.x, warp = tid >> 5, lane = tid & 31;
    int row0 = blockIdx.x * 128;
    int b = row0 >> 11, n0 = row0 & 2047;
    if (tid < 64) sAsum[tid] = 0.f;
    if (tid < CC) {
        float inv = 1.0f / (float)BN_TOT;
        float mean = g_colsum[tid] * inv;
        float var  = g_colsq[tid] * inv - mean * mean;
        float sc = rsqrtf(var + BN_EPS_F) * gamma[tid];
        sSc[tid] = sc;
        sBi[tid] = beta[tid] - mean * sc;
    }
    __syncthreads();
    float sc0 = sSc[lane],      bi0 = sBi[lane];
    float sc1 = sSc[lane + 32], bi1 = sBi[lane + 32];
    float sc2 = 0.f, bi2 = -1e30f;
    if (lane < 16) { sc2 = sSc[lane + 64]; bi2 = sBi[lane + 64]; }
    float acc0 = 0.f, acc1 = 0.f;
    #pragma unroll
    for (int it = 0; it < 8; ++it) {
        int nlA = warp + it * 16, nlB = nlA + 8;
        const __half* pa = g_assn + (size_t)(row0 + nlA) * CC;
        const __half* pb = g_assn + (size_t)(row0 + nlB) * CC;
        float a0 = __half2float(pa[lane]) * sc0 + bi0;
        float b0 = __half2float(pb[lane]) * sc0 + bi0;
        float a1 = __half2float(pa[lane + 32]) * sc1 + bi1;
        float b1 = __half2float(pb[lane + 32]) * sc1 + bi1;
        float a2 = (lane < 16) ? (__half2float(pa[lane + 64]) * sc2 + bi2) : -1e30f;
        float b2 = (lane < 16) ? (__half2float(pb[lane + 64]) * sc2 + bi2) : -1e30f;
        float ea0 = __expf(a0), ea1 = __expf(a1);
        float eb0 = __expf(b0), eb1 = __expf(b1);
        float ea2 = __expf(a2), eb2 = __expf(b2);   // -1e30 -> 0
        float sa = ea0 + ea1 + ea2;
        float sb = eb0 + eb1 + eb2;
        #pragma unroll
        for (int o = 16; o; o >>= 1) {
            sa += __shfl_xor_sync(0xffffffffu, sa, o);
            sb += __shfl_xor_sync(0xffffffffu, sb, o);
        }
        float ia = 1.0f / sa, ib = 1.0f / sb;
        float pA0 = ea0 * ia, pA1 = ea1 * ia;
        float pB0 = eb0 * ib, pB1 = eb1 * ib;
        acc0 += pA0 + pB0; acc1 += pA1 + pB1;
        sT[lane * STS + nlA]        = __float2half(pA0);
        sT[(lane + 32) * STS + nlA] = __float2half(pA1);
        sT[lane * STS + nlB]        = __float2half(pB0);
        sT[(lane + 32) * STS + nlB] = __float2half(pB1);
    }
    atomicAdd(&sAsum[lane], acc0);
    atomicAdd(&sAsum[lane + 32], acc1);
    __syncthreads();
    int kc = tid >> 2, seg = tid & 3;
    size_t base = ((size_t)(b * KC + kc)) * NN + n0 + seg * 32;
    const __half* src = &sT[kc * STS + seg * 32];
    #pragma unroll
    for (int j = 0; j < 8; ++j)
        *(uint2*)&g_assnT[base + j * 4] = *(const uint2*)&src[j * 4];
    if (tid < 64) atomicAdd(&g_asum[b * KC + tid], sAsum[tid]);
}

// ---------------- kernel 3: vlad^T = assn^T @ x - a_sum*clusters2 — 4-STAGE, ldsm A+B ----------------
// grid 256 (32 b x 8 d-tiles of 64), 256 thr. n-chunks of 32, 4-stage cp.async, ONE sync/iter.
// A fragments via ldmatrix.x4 (non-trans), B via ldmatrix.x4.trans. smem 38.9KB.
#define SAW 40    // assnT tile width: 32 + 8 pad (halfs); row stride 80B
#define SBW 72    // x tile width: 64 + 8 pad (halfs); row stride 144B
__global__ void __launch_bounds__(256, 2) k_gemm2(const float* __restrict__ clusters2) {
    __shared__ __align__(16) __half sA[4][64 * SAW];    // assnT tile [kc][n32]
    __shared__ __align__(16) __half sB[4][32 * SBW];    // x tile [n32][d64]
    int tid = threadIdx.x, warp = tid >> 5, lane = tid & 31;
    int g = lane >> 2, t = lane & 3;
    int wk = warp >> 2, wd = warp & 3;
    int b = blockIdx.x >> 3;
    int d0 = (blockIdx.x & 7) * 64;
    float acc[2][2][4] = {};
    const __half* Abase = g_assnT + (size_t)b * KC * NN;
    const __half* Bbase = g_xh + (size_t)b * NN * DD + d0;

    const int a_r = tid >> 2, a_c = tid & 3;            // sA: 64 rows x 4 16B-chunks
    const int b_r = tid >> 3, b_c = tid & 7;            // sB: 32 rows x 8 16B-chunks
    const int lrow = lane & 15, lhi = (lane >> 4) * 8;  // ldsm addressing (A and B)
    // prologue: issue stages 0,1,2 (group index == stage index)
    #pragma unroll
    for (int p = 0; p < 3; ++p) {
        cpasync16(&sA[p][a_r * SAW + a_c * 8], &Abase[(size_t)a_r * NN + p * 32 + a_c * 8]);
        cpasync16(&sB[p][b_r * SBW + b_c * 8], &Bbase[(size_t)(p * 32 + b_r) * DD + b_c * 8]);
        asm volatile("cp.async.commit_group;\n");
    }
    for (int s = 0; s < 64; ++s) {
        int buf = s & 3;
        if (s <= 61)      { asm volatile("cp.async.wait_group 2;\n"); }
        else if (s == 62) { asm volatile("cp.async.wait_group 1;\n"); }
        else              { asm volatile("cp.async.wait_group 0;\n"); }
        __syncthreads();   // stage s visible; all warps done reading stage s-1
        if (s + 3 < 64) {
            int nb = (s + 3) & 3, nn0 = (s + 3) * 32;   // (s+3)%4 == (s-1)%4: reads finished
            cpasync16(&sA[nb][a_r * SAW + a_c * 8], &Abase[(size_t)a_r * NN + nn0 + a_c * 8]);
            cpasync16(&sB[nb][b_r * SBW + b_c * 8], &Bbase[(size_t)(nn0 + b_r) * DD + b_c * 8]);
            asm volatile("cp.async.commit_group;\n");
        }
        #pragma unroll
        for (int ks = 0; ks < 32; ks += 16) {
            uint32_t af[2][4], bf[4];
            #pragma unroll
            for (int mf = 0; mf < 2; ++mf)
                ldsm_x4(af[mf], smemu32(&sA[buf][(wk * 32 + mf * 16 + lrow) * SAW + ks + lhi]));
            ldsm_x4_t(bf, smemu32(&sB[buf][(ks + lrow) * SBW + wd * 16 + lhi]));
            #pragma unroll
            for (int mf = 0; mf < 2; ++mf) {
                mma16816(acc[mf][0], af[mf], &bf[0]);
                mma16816(acc[mf][1], af[mf], &bf[2]);
            }
        }
        // no second sync: next iteration's sync protects buffer reuse
    }
    // epilogue: subtract a_sum*clusters2, write vladT fp32, accumulate column sq-norms
    #pragma unroll
    for (int mf = 0; mf < 2; ++mf) {
        #pragma unroll
        for (int h = 0; h < 2; ++h) {
            int kc = wk * 32 + mf * 16 + g + h * 8;
            float asv = g_asum[b * KC + kc];
            float nsq = 0.f;
            #pragma unroll
            for (int nf = 0; nf < 2; ++nf) {
                int d = d0 + wd * 16 + nf * 8 + 2 * t;
                float v0 = acc[mf][nf][h * 2 + 0] - asv * clusters2[(size_t)d * KC + kc];
                float v1 = acc[mf][nf][h * 2 + 1] - asv * clusters2[(size_t)(d + 1) * KC + kc];
                *(float2*)&g_vladT[((size_t)b * KC + kc) * DD + d] = make_float2(v0, v1);
                nsq += v0 * v0 + v1 * v1;
            }
            nsq += __shfl_xor_sync(0xffffffffu, nsq, 1);
            nsq += __shfl_xor_sync(0xffffffffu, nsq, 2);
            if (t == 0) atomicAdd(&g_colnorm[b * KC + kc], nsq);
        }
    }
}

// ---------------- kernel 4: (scales fused) + scale + transpose to out[b][d][k] ----------------
__global__ void __launch_bounds__(256) k_output(float* __restrict__ out) {
    __shared__ float sT[64][65];
    __shared__ float sR[64], sC[64];
    __shared__ float sTot;
    int tid = threadIdx.x;
    int b = blockIdx.x >> 3;
    int d0 = (blockIdx.x & 7) * 64;
    if (tid < 64) {
        float nsq = g_colnorm[b * KC + tid];
        float r = 1.0f / fmaxf(sqrtf(nsq), 1e-12f);
        sR[tid] = r;
        sC[tid] = nsq * r * r;   // ||col||^2 after intra-norm
    }
    __syncthreads();
    if (tid < 32) {
        float s = sC[tid] + sC[tid + 32];
        #pragma unroll
        for (int o = 16; o; o >>= 1) s += __shfl_xor_sync(0xffffffffu, s, o);
        if (tid == 0) sTot = s;
    }
    __syncthreads();
    float ginv = 1.0f / fmaxf(sqrtf(sTot), 1e-12f);
    {
        int kc = tid >> 2, seg = tid & 3;
        float s = sR[kc] * ginv;
        const float* src = &g_vladT[((size_t)b * KC + kc) * DD + d0 + seg * 16];
        #pragma unroll
        for (int j = 0; j < 4; ++j) {
            float4 v = *(const float4*)&src[j * 4];
            sT[kc][seg * 16 + j * 4 + 0] = v.x * s;
            sT[kc][seg * 16 + j * 4 + 1] = v.y * s;
            sT[kc][seg * 16 + j * 4 + 2] = v.z * s;
            sT[kc][seg * 16 + j * 4 + 3] = v.w * s;
        }
    }
    __syncthreads();
    {
        int d = tid >> 2, k0 = (tid & 3) * 16;
        float* dst = &out[(size_t)b * (DD * KC) + (size_t)(d0 + d) * KC + k0];
        #pragma unroll
        for (int j = 0; j < 4; ++j) {
            float4 v;
            v.x = sT[k0 + j * 4 + 0][d];
            v.y = sT[k0 + j * 4 + 1][d];
            v.z = sT[k0 + j * 4 + 2][d];
            v.w = sT[k0 + j * 4 + 3][d];
            *(float4*)&dst[j * 4] = v;
        }
    }
}

// ---------------- launch ----------------
extern "C" void kernel_launch(void* const* d_in, const int* in_sizes, int n_in,
                              void* d_out, int out_size) {
    (void)in_sizes; (void)n_in; (void)out_size;
    const float* x         = (const float*)d_in[0];
    const float* clusters  = (const float*)d_in[1];
    const float* clusters2 = (const float*)d_in[2];
    const float* gamma     = (const float*)d_in[3];
    const float* beta      = (const float*)d_in[4];
    float* out = (float*)d_out;

    k_init<<<64, 256>>>(clusters);
    k_gemm1<<<512, 256>>>(x);
    k_softmax<<<512, 256>>>(gamma, beta);
    k_gemm2<<<256, 256>>>(clusters2);
    k_output<<<256, 256>>>(out);
}